// round 6
// baseline (speedup 1.0000x reference)
#include <cuda_runtime.h>
#include <cuda_bf16.h>
#include <cstdint>

#define TD 768
#define TO 768
#define TE 8
#define TH 7680
#define TN 4096

#define BM 128
#define BN 128
#define BK 32
#define NTHREADS 256
#define SLD 40                      // smem row stride in bf16 (80 B)
#define PLANE_B (128 * SLD * 2)     // 10240
#define STAGE_B (4 * PLANE_B)       // 40960
#define NSTAGE 3

#define SM_BIAS  0
#define SM_PROB  512
#define SM_TILES 1024
#define SM_STAGE 1024
#define SM_TOTAL (1024 + NSTAGE * STAGE_B)   // 123904

// ---- scratch ----
__device__ int   g_counts[TE];
__device__ int   g_offsets[TE];
__device__ int   g_rank[TN];
__device__ int   g_eidx[TN];
__device__ float g_prob[TN];
__device__ int   g_perm[TN];
__device__ __nv_bfloat16 g_xp_hi[(size_t)TN * TD];
__device__ __nv_bfloat16 g_xp_lo[(size_t)TN * TD];
__device__ __nv_bfloat16 g_h_hi[(size_t)TN * TH];
__device__ __nv_bfloat16 g_h_lo[(size_t)TN * TH];
__device__ __nv_bfloat16 g_w1t_hi[(size_t)TE * TH * TD];   // [e][n][k]
__device__ __nv_bfloat16 g_w1t_lo[(size_t)TE * TH * TD];
__device__ __nv_bfloat16 g_w2t_hi[(size_t)TE * TO * TH];   // [e][n][k]
__device__ __nv_bfloat16 g_w2t_lo[(size_t)TE * TO * TH];

// ================= helpers =================
__device__ __forceinline__ uint32_t smem_to_u32(const void* p) {
    uint32_t a;
    asm("{ .reg .u64 t; cvta.to.shared.u64 t, %1; cvt.u32.u64 %0, t; }" : "=r"(a) : "l"(p));
    return a;
}
__device__ __forceinline__ void ldsm4(uint32_t* r, uint32_t addr) {
    asm volatile("ldmatrix.sync.aligned.m8n8.x4.shared.b16 {%0,%1,%2,%3}, [%4];"
                 : "=r"(r[0]), "=r"(r[1]), "=r"(r[2]), "=r"(r[3]) : "r"(addr));
}
__device__ __forceinline__ void mma16816(float* c, const uint32_t* a, const uint32_t* b) {
    asm volatile("mma.sync.aligned.m16n8k16.row.col.f32.bf16.bf16.f32 "
                 "{%0,%1,%2,%3}, {%4,%5,%6,%7}, {%8,%9}, {%0,%1,%2,%3};"
                 : "+f"(c[0]), "+f"(c[1]), "+f"(c[2]), "+f"(c[3])
                 : "r"(a[0]), "r"(a[1]), "r"(a[2]), "r"(a[3]), "r"(b[0]), "r"(b[1]));
}
__device__ __forceinline__ void split2(float a, float b, uint32_t& hi, uint32_t& lo) {
    __nv_bfloat16 ah = __float2bfloat16(a);
    __nv_bfloat16 bh = __float2bfloat16(b);
    __nv_bfloat16 al = __float2bfloat16(a - __bfloat162float(ah));
    __nv_bfloat16 bl = __float2bfloat16(b - __bfloat162float(bh));
    hi = (uint32_t)__bfloat16_as_ushort(ah) | ((uint32_t)__bfloat16_as_ushort(bh) << 16);
    lo = (uint32_t)__bfloat16_as_ushort(al) | ((uint32_t)__bfloat16_as_ushort(bl) << 16);
}

#define CPA16(d, s)  asm volatile("cp.async.ca.shared.global [%0], [%1], 16;" :: "r"(d), "l"(s))
#define CP_COMMIT()  asm volatile("cp.async.commit_group;" ::: "memory")
#define CP_WAIT1()   asm volatile("cp.async.wait_group 1;" ::: "memory")
#define CP_WAIT0()   asm volatile("cp.async.wait_group 0;" ::: "memory")

// ================= gating / routing =================
__global__ void k_zero() {
    if (threadIdx.x < TE) g_counts[threadIdx.x] = 0;
}

__global__ void k_gate(const float* __restrict__ x, const float* __restrict__ Wg,
                       const float* __restrict__ bg) {
    int warp = (blockIdx.x * blockDim.x + threadIdx.x) >> 5;
    int lane = threadIdx.x & 31;
    if (warp >= TN) return;
    const float* xr = x + (size_t)warp * TD;
    float acc[TE];
#pragma unroll
    for (int e = 0; e < TE; e++) acc[e] = 0.f;
    for (int d = lane; d < TD; d += 32) {
        float xv = xr[d];
        const float* wr = Wg + (size_t)d * TE;
#pragma unroll
        for (int e = 0; e < TE; e++) acc[e] += xv * wr[e];
    }
#pragma unroll
    for (int e = 0; e < TE; e++) {
        float v = acc[e];
#pragma unroll
        for (int off = 16; off > 0; off >>= 1) v += __shfl_xor_sync(0xffffffffu, v, off);
        acc[e] = v;
    }
    if (lane == 0) {
        float mx = -1e30f; int am = 0;
#pragma unroll
        for (int e = 0; e < TE; e++) {
            float l = acc[e] + bg[e];
            acc[e] = l;
            if (l > mx) { mx = l; am = e; }
        }
        float s = 0.f;
#pragma unroll
        for (int e = 0; e < TE; e++) s += expf(acc[e] - mx);
        g_eidx[warp] = am;
        g_prob[warp] = 1.f / s;
        g_rank[warp] = atomicAdd(&g_counts[am], 1);
    }
}

__global__ void k_scan() {
    int o = 0;
#pragma unroll
    for (int e = 0; e < TE; e++) { g_offsets[e] = o; o += g_counts[e]; }
}

__global__ void k_scatter() {
    int n = blockIdx.x * blockDim.x + threadIdx.x;
    if (n < TN) g_perm[g_offsets[g_eidx[n]] + g_rank[n]] = n;
}

// ================= pre-convert =================
// x -> permuted hi/lo bf16 planes. grid = TN blocks of 192 threads.
__global__ void k_convert_x(const float* __restrict__ x) {
    const int pos = blockIdx.x;
    const int t = threadIdx.x;                 // 0..191 (192*4 = 768)
    const int token = g_perm[pos];
    float4 v = *(const float4*)(x + (size_t)token * TD + t * 4);
    uint32_t h0, l0, h1, l1;
    split2(v.x, v.y, h0, l0);
    split2(v.z, v.w, h1, l1);
    uint16_t* H = (uint16_t*)g_xp_hi + (size_t)pos * TD + t * 4;
    uint16_t* L = (uint16_t*)g_xp_lo + (size_t)pos * TD + t * 4;
    *(uint2*)H = make_uint2(h0, h1);
    *(uint2*)L = make_uint2(l0, l1);
}

// W [e][k][n] fp32  ->  Wt [e][n][k] bf16 hi/lo. 32x32 tiles, 256 threads.
__global__ void k_convert_wT(const float* __restrict__ W, int which) {
    __shared__ uint16_t shh[32][36];
    __shared__ uint16_t shl[32][36];
    const int ndim = which ? TO : TH;
    const int kdim = which ? TH : TD;
    uint16_t* oh = (uint16_t*)(which ? g_w2t_hi : g_w1t_hi);
    uint16_t* ol = (uint16_t*)(which ? g_w2t_lo : g_w1t_lo);
    const int n0 = blockIdx.x * 32, k0 = blockIdx.y * 32, e = blockIdx.z;
    const float* Wp = W + (size_t)e * kdim * ndim;
    const int t = threadIdx.x, tx = t & 31, ty = t >> 5;
#pragma unroll
    for (int q = 0; q < 4; q++) {
        const int k = ty * 4 + q;
        float v = Wp[(size_t)(k0 + k) * ndim + n0 + tx];
        __nv_bfloat16 hb = __float2bfloat16(v);
        shh[tx][k] = __bfloat16_as_ushort(hb);
        shl[tx][k] = __bfloat16_as_ushort(__float2bfloat16(v - __bfloat162float(hb)));
    }
    __syncthreads();
    const int n = t >> 3, c = t & 7;
    uint2 vh = *(uint2*)&shh[n][c * 4];
    uint2 vl = *(uint2*)&shl[n][c * 4];
    const size_t off = (size_t)e * ndim * kdim + (size_t)(n0 + n) * kdim + k0 + c * 4;
    *(uint2*)(oh + off) = vh;
    *(uint2*)(ol + off) = vl;
}

// ================= mma compute core (layout identical to passing R5) =================
struct Frag { float c[4][4][4]; };

__device__ __forceinline__ void compute_stage(uint32_t tb, int wm, int wn, int lane,
                                              Frag& F) {
    const uint32_t aoff = ((uint32_t)((wm * 64 + (lane & 15)) * SLD + (lane >> 4) * 8)) * 2;
    const uint32_t boff = ((uint32_t)((wn * 32 + ((lane >> 4) & 1) * 8 + (lane & 7)) * SLD
                                      + ((lane >> 3) & 1) * 8)) * 2;
    const uint32_t aHi = tb + aoff;
    const uint32_t aLo = tb + PLANE_B + aoff;
    const uint32_t bHi = tb + 2 * PLANE_B + boff;
    const uint32_t bLo = tb + 3 * PLANE_B + boff;
#pragma unroll
    for (int ks = 0; ks < 2; ks++) {
        const uint32_t kso = ks * 32;
        uint32_t ah[4][4], bh[2][4];
#pragma unroll
        for (int mt = 0; mt < 4; mt++) ldsm4(ah[mt], aHi + mt * 16 * SLD * 2 + kso);
#pragma unroll
        for (int p = 0; p < 2; p++) ldsm4(bh[p], bHi + p * 16 * SLD * 2 + kso);
#pragma unroll
        for (int mt = 0; mt < 4; mt++)
#pragma unroll
            for (int nt = 0; nt < 4; nt++)
                mma16816(F.c[mt][nt], ah[mt], &bh[nt >> 1][(nt & 1) * 2]);
        uint32_t bl[2][4];
#pragma unroll
        for (int p = 0; p < 2; p++) ldsm4(bl[p], bLo + p * 16 * SLD * 2 + kso);
#pragma unroll
        for (int mt = 0; mt < 4; mt++)
#pragma unroll
            for (int nt = 0; nt < 4; nt++)
                mma16816(F.c[mt][nt], ah[mt], &bl[nt >> 1][(nt & 1) * 2]);
        uint32_t al[4][4];
#pragma unroll
        for (int mt = 0; mt < 4; mt++) ldsm4(al[mt], aLo + mt * 16 * SLD * 2 + kso);
#pragma unroll
        for (int mt = 0; mt < 4; mt++)
#pragma unroll
            for (int nt = 0; nt < 4; nt++)
                mma16816(F.c[mt][nt], al[mt], &bh[nt >> 1][(nt & 1) * 2]);
    }
}

// per-thread stage fill: thread owns (row r = tid&127, half hh = tid>>7) of all 4 planes
__device__ __forceinline__ void fill_stage(uint32_t db, uint32_t drow,
                                           const char* aH, const char* aL,
                                           const char* bH, const char* bL,
                                           uint32_t koff) {
    uint32_t d0 = db + drow;
    CPA16(d0,      aH + koff);
    CPA16(d0 + 16, aH + koff + 16);
    uint32_t d1 = d0 + PLANE_B;
    CPA16(d1,      aL + koff);
    CPA16(d1 + 16, aL + koff + 16);
    uint32_t d2 = d1 + PLANE_B;
    CPA16(d2,      bH + koff);
    CPA16(d2 + 16, bH + koff + 16);
    uint32_t d3 = d2 + PLANE_B;
    CPA16(d3,      bL + koff);
    CPA16(d3 + 16, bL + koff + 16);
}

// ================= GEMM1 =================
__global__ void __launch_bounds__(NTHREADS) k_gemm1(const float* __restrict__ b1) {
    extern __shared__ char smem[];
    const int e   = blockIdx.z;
    const int cnt = g_counts[e];
    const int m0  = blockIdx.y * BM;
    if (m0 >= cnt) return;
    const int n0   = blockIdx.x * BN;
    const int base = g_offsets[e];

    const uint32_t sb = smem_to_u32(smem);
    const int tid = threadIdx.x, wid = tid >> 5, lane = tid & 31;
    const int wm = wid & 1, wn = wid >> 1;

    if (tid < 128) *(float*)(smem + SM_BIAS + tid * 4) = b1[(size_t)e * TH + n0 + tid];

    const int r  = tid & 127, hh = tid >> 7;
    const int ar = base + ((m0 + r < cnt) ? (m0 + r) : (cnt - 1));
    const char* aH = (const char*)((const uint16_t*)g_xp_hi + (size_t)ar * TD) + hh * 32;
    const char* aL = (const char*)((const uint16_t*)g_xp_lo + (size_t)ar * TD) + hh * 32;
    const char* bH = (const char*)((const uint16_t*)g_w1t_hi + (size_t)e * TH * TD
                                   + (size_t)(n0 + r) * TD) + hh * 32;
    const char* bL = (const char*)((const uint16_t*)g_w1t_lo + (size_t)e * TH * TD
                                   + (size_t)(n0 + r) * TD) + hh * 32;
    const uint32_t drow = (uint32_t)(r * 80 + hh * 32);

    Frag F;
#pragma unroll
    for (int mt = 0; mt < 4; mt++)
#pragma unroll
        for (int nt = 0; nt < 4; nt++)
#pragma unroll
            for (int i = 0; i < 4; i++) F.c[mt][nt][i] = 0.f;

    const int NS = TD / BK;  // 24
    fill_stage(sb + SM_TILES,           drow, aH, aL, bH, bL, 0);  CP_COMMIT();
    fill_stage(sb + SM_TILES + STAGE_B, drow, aH, aL, bH, bL, 64); CP_COMMIT();
    for (int s = 0; s < NS; s++) {
        if (s == NS - 1) { CP_WAIT0(); } else { CP_WAIT1(); }
        __syncthreads();
        if (s + 2 < NS) {
            fill_stage(sb + SM_TILES + ((s + 2) % NSTAGE) * STAGE_B, drow,
                       aH, aL, bH, bL, (uint32_t)(s + 2) * 64);
            CP_COMMIT();
        }
        compute_stage(sb + SM_TILES + (s % NSTAGE) * STAGE_B, wm, wn, lane, F);
        __syncthreads();
    }

    // epilogue: relu(+bias) -> bf16 hi/lo staged -> coalesced g_h stores
#pragma unroll
    for (int mt = 0; mt < 4; mt++) {
        const int r0 = wm * 64 + mt * 16 + (lane >> 2);
        const int r1 = r0 + 8;
#pragma unroll
        for (int nt = 0; nt < 4; nt++) {
            const int cp = wn * 16 + nt * 4 + (lane & 3);
            float b0  = *(float*)(smem + SM_BIAS + (2 * cp) * 4);
            float b1v = *(float*)(smem + SM_BIAS + (2 * cp + 1) * 4);
            uint32_t h, l;
            split2(fmaxf(F.c[mt][nt][0] + b0, 0.f), fmaxf(F.c[mt][nt][1] + b1v, 0.f), h, l);
            *(uint32_t*)(smem + SM_STAGE + (r0 * 64 + cp) * 4) = h;
            *(uint32_t*)(smem + SM_STAGE + 32768 + (r0 * 64 + cp) * 4) = l;
            split2(fmaxf(F.c[mt][nt][2] + b0, 0.f), fmaxf(F.c[mt][nt][3] + b1v, 0.f), h, l);
            *(uint32_t*)(smem + SM_STAGE + (r1 * 64 + cp) * 4) = h;
            *(uint32_t*)(smem + SM_STAGE + 32768 + (r1 * 64 + cp) * 4) = l;
        }
    }
    __syncthreads();
    {
        const int rr = tid >> 1, part = tid & 1;
        if (rr < cnt - m0) {
            const size_t gro = (size_t)(base + m0 + rr) * TH + n0;
            uint16_t* HP = (uint16_t*)g_h_hi;
            uint16_t* LP = (uint16_t*)g_h_lo;
#pragma unroll
            for (int j = 0; j < 8; j++) {
                uint4 qh = *(uint4*)(smem + SM_STAGE + (rr * 64 + part * 32 + j * 4) * 4);
                uint4 ql = *(uint4*)(smem + SM_STAGE + 32768 + (rr * 64 + part * 32 + j * 4) * 4);
                *(uint4*)(HP + gro + part * 64 + j * 8) = qh;
                *(uint4*)(LP + gro + part * 64 + j * 8) = ql;
            }
        }
    }
}

// ================= GEMM2 =================
__global__ void __launch_bounds__(NTHREADS) k_gemm2(const float* __restrict__ b2,
                                                    float* __restrict__ out) {
    extern __shared__ char smem[];
    const int e   = blockIdx.z;
    const int cnt = g_counts[e];
    const int m0  = blockIdx.y * BM;
    if (m0 >= cnt) return;
    const int n0   = blockIdx.x * BN;
    const int base = g_offsets[e];

    const uint32_t sb = smem_to_u32(smem);
    const int tid = threadIdx.x, wid = tid >> 5, lane = tid & 31;
    const int wm = wid & 1, wn = wid >> 1;

    if (tid < 128) {
        *(float*)(smem + SM_BIAS + tid * 4) = b2[(size_t)e * TO + n0 + tid];
        const int rc = (m0 + tid < cnt) ? (m0 + tid) : (cnt - 1);
        *(float*)(smem + SM_PROB + tid * 4) = g_prob[g_perm[base + rc]];
    }

    const int r  = tid & 127, hh = tid >> 7;
    const int ar = base + ((m0 + r < cnt) ? (m0 + r) : (cnt - 1));
    const char* aH = (const char*)((const uint16_t*)g_h_hi + (size_t)ar * TH) + hh * 32;
    const char* aL = (const char*)((const uint16_t*)g_h_lo + (size_t)ar * TH) + hh * 32;
    const char* bH = (const char*)((const uint16_t*)g_w2t_hi + (size_t)e * TO * TH
                                   + (size_t)(n0 + r) * TH) + hh * 32;
    const char* bL = (const char*)((const uint16_t*)g_w2t_lo + (size_t)e * TO * TH
                                   + (size_t)(n0 + r) * TH) + hh * 32;
    const uint32_t drow = (uint32_t)(r * 80 + hh * 32);

    Frag F;
#pragma unroll
    for (int mt = 0; mt < 4; mt++)
#pragma unroll
        for (int nt = 0; nt < 4; nt++)
#pragma unroll
            for (int i = 0; i < 4; i++) F.c[mt][nt][i] = 0.f;

    const int NS = TH / BK;  // 240
    fill_stage(sb + SM_TILES,           drow, aH, aL, bH, bL, 0);  CP_COMMIT();
    fill_stage(sb + SM_TILES + STAGE_B, drow, aH, aL, bH, bL, 64); CP_COMMIT();
    for (int s = 0; s < NS; s++) {
        if (s == NS - 1) { CP_WAIT0(); } else { CP_WAIT1(); }
        __syncthreads();
        if (s + 2 < NS) {
            fill_stage(sb + SM_TILES + ((s + 2) % NSTAGE) * STAGE_B, drow,
                       aH, aL, bH, bL, (uint32_t)(s + 2) * 64);
            CP_COMMIT();
        }
        compute_stage(sb + SM_TILES + (s % NSTAGE) * STAGE_B, wm, wn, lane, F);
        __syncthreads();
    }

    // epilogue: (c + bias) * prob -> fp32 stage -> scattered coalesced stores
#pragma unroll
    for (int mt = 0; mt < 4; mt++) {
        const int r0 = wm * 64 + mt * 16 + (lane >> 2);
        const int r1 = r0 + 8;
        const float p0 = *(float*)(smem + SM_PROB + r0 * 4);
        const float p1 = *(float*)(smem + SM_PROB + r1 * 4);
#pragma unroll
        for (int nt = 0; nt < 4; nt++) {
            const int col = wn * 32 + nt * 8 + (lane & 3) * 2;
            float b0  = *(float*)(smem + SM_BIAS + col * 4);
            float b1v = *(float*)(smem + SM_BIAS + (col + 1) * 4);
            *(float*)(smem + SM_STAGE + (r0 * 128 + col) * 4)     = p0 * (F.c[mt][nt][0] + b0);
            *(float*)(smem + SM_STAGE + (r0 * 128 + col + 1) * 4) = p0 * (F.c[mt][nt][1] + b1v);
            *(float*)(smem + SM_STAGE + (r1 * 128 + col) * 4)     = p1 * (F.c[mt][nt][2] + b0);
            *(float*)(smem + SM_STAGE + (r1 * 128 + col + 1) * 4) = p1 * (F.c[mt][nt][3] + b1v);
        }
    }
    __syncthreads();
    {
        const int rr = tid >> 1, part = tid & 1;
        if (rr < cnt - m0) {
            const int token = g_perm[base + m0 + rr];
            float* op = out + (size_t)token * TO + n0 + part * 64;
#pragma unroll
            for (int j = 0; j < 16; j++) {
                float4 q = *(float4*)(smem + SM_STAGE + (rr * 128 + part * 64 + j * 4) * 4);
                *(float4*)(op + j * 4) = q;
            }
        }
    }
}

// ---------------------------------------------------------------
extern "C" void kernel_launch(void* const* d_in, const int* in_sizes, int n_in,
                              void* d_out, int out_size) {
    (void)in_sizes; (void)n_in; (void)out_size;
    const float* x  = (const float*)d_in[0];
    const float* Wg = (const float*)d_in[1];
    const float* bg = (const float*)d_in[2];
    const float* W1 = (const float*)d_in[3];
    const float* b1 = (const float*)d_in[4];
    const float* W2 = (const float*)d_in[5];
    const float* b2 = (const float*)d_in[6];
    float* out = (float*)d_out;

    cudaFuncSetAttribute(k_gemm1, cudaFuncAttributeMaxDynamicSharedMemorySize, SM_TOTAL);
    cudaFuncSetAttribute(k_gemm2, cudaFuncAttributeMaxDynamicSharedMemorySize, SM_TOTAL);

    k_zero<<<1, 32>>>();
    k_gate<<<(TN * 32 + 255) / 256, 256>>>(x, Wg, bg);
    k_scan<<<1, 1>>>();
    k_scatter<<<(TN + 255) / 256, 256>>>();
    k_convert_x<<<TN, 192>>>(x);
    k_convert_wT<<<dim3(TH / 32, TD / 32, TE), 256>>>(W1, 0);
    k_convert_wT<<<dim3(TO / 32, TH / 32, TE), 256>>>(W2, 1);
    k_gemm1<<<dim3(TH / BN, TN / BM, TE), NTHREADS, SM_TOTAL>>>(b1);
    k_gemm2<<<dim3(TO / BN, TN / BM, TE), NTHREADS, SM_TOTAL>>>(b2, out);
}

// round 9
// speedup vs baseline: 1.2624x; 1.2624x over previous
#include <cuda_runtime.h>
#include <cuda_bf16.h>
#include <cstdint>

#define TD 768
#define TO 768
#define TE 8
#define TH 7680
#define TN 4096

#define BM 128
#define BN 128
#define BK 32
#define NTHREADS 256
#define SLD 40                      // smem row stride in bf16 (80 B)
#define PLANE_B (128 * SLD * 2)     // 10240
#define STAGE_B (4 * PLANE_B)       // 40960

// SMEM layout (bytes)
#define SM_BIAS  0
#define SM_PROB  512
#define SM_TILES 1024
#define SM_STAGE 1024               // epilogue staging reuses tile space
#define SM_TOTAL (1024 + 2 * STAGE_B)   // 82944

// ---- scratch ----
__device__ int   g_counts[TE];
__device__ int   g_offsets[TE];
__device__ int   g_rank[TN];
__device__ int   g_eidx[TN];
__device__ float g_prob[TN];
__device__ int   g_perm[TN];
__device__ __nv_bfloat16 g_h_hi[(size_t)TN * TH];
__device__ __nv_bfloat16 g_h_lo[(size_t)TN * TH];

// ================= helpers =================
__device__ __forceinline__ uint32_t smem_to_u32(const void* p) {
    uint32_t a;
    asm("{ .reg .u64 t; cvta.to.shared.u64 t, %1; cvt.u32.u64 %0, t; }" : "=r"(a) : "l"(p));
    return a;
}
__device__ __forceinline__ void ldsm4(uint32_t* r, uint32_t addr) {
    asm volatile("ldmatrix.sync.aligned.m8n8.x4.shared.b16 {%0,%1,%2,%3}, [%4];"
                 : "=r"(r[0]), "=r"(r[1]), "=r"(r[2]), "=r"(r[3]) : "r"(addr));
}
__device__ __forceinline__ void mma16816(float* c, const uint32_t* a, const uint32_t* b) {
    asm volatile("mma.sync.aligned.m16n8k16.row.col.f32.bf16.bf16.f32 "
                 "{%0,%1,%2,%3}, {%4,%5,%6,%7}, {%8,%9}, {%0,%1,%2,%3};"
                 : "+f"(c[0]), "+f"(c[1]), "+f"(c[2]), "+f"(c[3])
                 : "r"(a[0]), "r"(a[1]), "r"(a[2]), "r"(a[3]), "r"(b[0]), "r"(b[1]));
}
__device__ __forceinline__ void split2(float a, float b, uint32_t& hi, uint32_t& lo) {
    __nv_bfloat16 ah = __float2bfloat16(a);
    __nv_bfloat16 bh = __float2bfloat16(b);
    __nv_bfloat16 al = __float2bfloat16(a - __bfloat162float(ah));
    __nv_bfloat16 bl = __float2bfloat16(b - __bfloat162float(bh));
    hi = (uint32_t)__bfloat16_as_ushort(ah) | ((uint32_t)__bfloat16_as_ushort(bh) << 16);
    lo = (uint32_t)__bfloat16_as_ushort(al) | ((uint32_t)__bfloat16_as_ushort(bl) << 16);
}

// ================= gating / routing =================
__global__ void k_zero() {
    if (threadIdx.x < TE) g_counts[threadIdx.x] = 0;
}

__global__ void k_gate(const float* __restrict__ x, const float* __restrict__ Wg,
                       const float* __restrict__ bg) {
    int warp = (blockIdx.x * blockDim.x + threadIdx.x) >> 5;
    int lane = threadIdx.x & 31;
    if (warp >= TN) return;
    const float* xr = x + (size_t)warp * TD;
    float acc[TE];
#pragma unroll
    for (int e = 0; e < TE; e++) acc[e] = 0.f;
    for (int d = lane; d < TD; d += 32) {
        float xv = xr[d];
        const float* wr = Wg + (size_t)d * TE;
#pragma unroll
        for (int e = 0; e < TE; e++) acc[e] += xv * wr[e];
    }
#pragma unroll
    for (int e = 0; e < TE; e++) {
        float v = acc[e];
#pragma unroll
        for (int off = 16; off > 0; off >>= 1) v += __shfl_xor_sync(0xffffffffu, v, off);
        acc[e] = v;
    }
    if (lane == 0) {
        float mx = -1e30f; int am = 0;
#pragma unroll
        for (int e = 0; e < TE; e++) {
            float l = acc[e] + bg[e];
            acc[e] = l;
            if (l > mx) { mx = l; am = e; }
        }
        float s = 0.f;
#pragma unroll
        for (int e = 0; e < TE; e++) s += expf(acc[e] - mx);
        g_eidx[warp] = am;
        g_prob[warp] = 1.f / s;
        g_rank[warp] = atomicAdd(&g_counts[am], 1);
    }
}

__global__ void k_scan() {
    int o = 0;
#pragma unroll
    for (int e = 0; e < TE; e++) { g_offsets[e] = o; o += g_counts[e]; }
}

__global__ void k_scatter() {
    int n = blockIdx.x * blockDim.x + threadIdx.x;
    if (n < TN) g_perm[g_offsets[g_eidx[n]] + g_rank[n]] = n;
}

// ================= mma compute core (identical to passing R5) =================
struct Frag { float c[4][4][4]; };

__device__ __forceinline__ void compute_stage(uint32_t tb, int wm, int wn, int lane,
                                              Frag& F) {
    const uint32_t aoff = ((uint32_t)((wm * 64 + (lane & 15)) * SLD + (lane >> 4) * 8)) * 2;
    const uint32_t boff = ((uint32_t)((wn * 32 + ((lane >> 4) & 1) * 8 + (lane & 7)) * SLD
                                      + ((lane >> 3) & 1) * 8)) * 2;
    const uint32_t aHi = tb + aoff;
    const uint32_t aLo = tb + PLANE_B + aoff;
    const uint32_t bHi = tb + 2 * PLANE_B + boff;
    const uint32_t bLo = tb + 3 * PLANE_B + boff;
#pragma unroll
    for (int ks = 0; ks < 2; ks++) {
        const uint32_t kso = ks * 32;
        uint32_t ah[4][4], bh[2][4];
#pragma unroll
        for (int mt = 0; mt < 4; mt++) ldsm4(ah[mt], aHi + mt * 16 * SLD * 2 + kso);
#pragma unroll
        for (int p = 0; p < 2; p++) ldsm4(bh[p], bHi + p * 16 * SLD * 2 + kso);
#pragma unroll
        for (int mt = 0; mt < 4; mt++)
#pragma unroll
            for (int nt = 0; nt < 4; nt++)
                mma16816(F.c[mt][nt], ah[mt], &bh[nt >> 1][(nt & 1) * 2]);
        uint32_t bl[2][4];
#pragma unroll
        for (int p = 0; p < 2; p++) ldsm4(bl[p], bLo + p * 16 * SLD * 2 + kso);
#pragma unroll
        for (int mt = 0; mt < 4; mt++)
#pragma unroll
            for (int nt = 0; nt < 4; nt++)
                mma16816(F.c[mt][nt], ah[mt], &bl[nt >> 1][(nt & 1) * 2]);
        uint32_t al[4][4];
#pragma unroll
        for (int mt = 0; mt < 4; mt++) ldsm4(al[mt], aLo + mt * 16 * SLD * 2 + kso);
#pragma unroll
        for (int mt = 0; mt < 4; mt++)
#pragma unroll
            for (int nt = 0; nt < 4; nt++)
                mma16816(F.c[mt][nt], al[mt], &bh[nt >> 1][(nt & 1) * 2]);
    }
}

// ---- B global loads (coalesced, lane = n), into regs ----
__device__ __forceinline__ void load_B(float* bw, const float* __restrict__ p0,
                                       const float* __restrict__ p1, int ldW, int k0) {
    const float* a = p0 + (size_t)k0 * ldW;
    const float* b = p1 + (size_t)k0 * ldW;
#pragma unroll
    for (int kk = 0; kk < 8; kk++) bw[kk] = a[(size_t)kk * ldW];
#pragma unroll
    for (int kk = 0; kk < 8; kk++) bw[8 + kk] = b[(size_t)kk * ldW];
}
// ---- B regs -> smem (split hi/lo, store uint4) ----
__device__ __forceinline__ void store_B(char* smem, const float* bw,
                                        uint32_t o0, uint32_t o1) {
    uint32_t hi[4], lo[4];
#pragma unroll
    for (int kk = 0; kk < 4; kk++) split2(bw[2 * kk], bw[2 * kk + 1], hi[kk], lo[kk]);
    *(uint4*)(smem + 2 * PLANE_B + o0) = *(uint4*)hi;
    *(uint4*)(smem + 3 * PLANE_B + o0) = *(uint4*)lo;
#pragma unroll
    for (int kk = 0; kk < 4; kk++) split2(bw[8 + 2 * kk], bw[9 + 2 * kk], hi[kk], lo[kk]);
    *(uint4*)(smem + 2 * PLANE_B + o1) = *(uint4*)hi;
    *(uint4*)(smem + 3 * PLANE_B + o1) = *(uint4*)lo;
}

// ================= GEMM1 =================
__global__ void __launch_bounds__(NTHREADS) k_gemm1(const float* __restrict__ x,
                                                    const float* __restrict__ W1,
                                                    const float* __restrict__ b1) {
    extern __shared__ char smem[];
    const int e   = blockIdx.z;
    const int cnt = g_counts[e];
    const int m0  = blockIdx.y * BM;
    if (m0 >= cnt) return;
    const int n0   = blockIdx.x * BN;
    const int base = g_offsets[e];
    const float* W = W1 + (size_t)e * TD * TH;

    const uint32_t sb = smem_to_u32(smem);
    char* tiles = smem + SM_TILES;
    const int tid = threadIdx.x, wid = tid >> 5, lane = tid & 31;
    const int wm = wid & 1, wn = wid >> 1;

    if (tid < 128) *(float*)(smem + SM_BIAS + tid * 4) = b1[(size_t)e * TH + n0 + tid];

    const int arow = tid >> 1;
    const int half = tid & 1;
    const int arowc = (m0 + arow < cnt) ? (m0 + arow) : (cnt - 1);
    const float* aptr = x + (size_t)g_perm[base + arowc] * TD + half * 16;
    const uint32_t aso = ((uint32_t)(arow * SLD + half * 16)) * 2;

    // B task decomposition (same mapping as R5's fill_B)
    const int n_b0 = ((wid) & 3) * 32 + lane,  kg_b0 = (wid) >> 2;
    const int n_b1 = ((wid + 8) & 3) * 32 + lane, kg_b1 = (wid + 8) >> 2;
    const float* bp0 = W + (size_t)(kg_b0 * 8) * TH + n0 + n_b0;
    const float* bp1 = W + (size_t)(kg_b1 * 8) * TH + n0 + n_b1;
    const uint32_t bo0 = ((uint32_t)(n_b0 * SLD + kg_b0 * 8)) * 2;
    const uint32_t bo1 = ((uint32_t)(n_b1 * SLD + kg_b1 * 8)) * 2;

    Frag F;
#pragma unroll
    for (int mt = 0; mt < 4; mt++)
#pragma unroll
        for (int nt = 0; nt < 4; nt++)
#pragma unroll
            for (int i = 0; i < 4; i++) F.c[mt][nt][i] = 0.f;

    float4 av[4];
    float  bw[16];

    // preload + convert stage 0 into buf0
#pragma unroll
    for (int q = 0; q < 4; q++) av[q] = *(const float4*)(aptr + q * 4);
    load_B(bw, bp0, bp1, TH, 0);
    {
#pragma unroll
        for (int q = 0; q < 4; q++) {
            uint32_t h0, l0, h1, l1;
            split2(av[q].x, av[q].y, h0, l0);
            split2(av[q].z, av[q].w, h1, l1);
            const uint32_t o = aso + (uint32_t)q * 8;
            *(uint32_t*)(tiles + o) = h0;
            *(uint32_t*)(tiles + o + 4) = h1;
            *(uint32_t*)(tiles + PLANE_B + o) = l0;
            *(uint32_t*)(tiles + PLANE_B + o + 4) = l1;
        }
        store_B(tiles, bw, bo0, bo1);
    }
    __syncthreads();

    const int NS = TD / BK;  // 24
    for (int s = 0; s < NS; s++) {
        if (s + 1 < NS) {
            const int k0 = (s + 1) * BK;
#pragma unroll
            for (int q = 0; q < 4; q++) av[q] = *(const float4*)(aptr + k0 + q * 4);
            load_B(bw, bp0, bp1, TH, k0);
        }
        compute_stage(sb + SM_TILES + (uint32_t)(s & 1) * STAGE_B, wm, wn, lane, F);
        if (s + 1 < NS) {
            char* nb = tiles + ((s + 1) & 1) * STAGE_B;
#pragma unroll
            for (int q = 0; q < 4; q++) {
                uint32_t h0, l0, h1, l1;
                split2(av[q].x, av[q].y, h0, l0);
                split2(av[q].z, av[q].w, h1, l1);
                const uint32_t o = aso + (uint32_t)q * 8;
                *(uint32_t*)(nb + o) = h0;
                *(uint32_t*)(nb + o + 4) = h1;
                *(uint32_t*)(nb + PLANE_B + o) = l0;
                *(uint32_t*)(nb + PLANE_B + o + 4) = l1;
            }
            store_B(nb, bw, bo0, bo1);
        }
        __syncthreads();
    }

    // epilogue: relu(+bias) -> bf16 hi/lo staged -> coalesced g_h stores
#pragma unroll
    for (int mt = 0; mt < 4; mt++) {
        const int r0 = wm * 64 + mt * 16 + (lane >> 2);
        const int r1 = r0 + 8;
#pragma unroll
        for (int nt = 0; nt < 4; nt++) {
            const int cp = wn * 16 + nt * 4 + (lane & 3);
            float b0  = *(float*)(smem + SM_BIAS + (2 * cp) * 4);
            float b1v = *(float*)(smem + SM_BIAS + (2 * cp + 1) * 4);
            uint32_t h, l;
            split2(fmaxf(F.c[mt][nt][0] + b0, 0.f), fmaxf(F.c[mt][nt][1] + b1v, 0.f), h, l);
            *(uint32_t*)(smem + SM_STAGE + (r0 * 64 + cp) * 4) = h;
            *(uint32_t*)(smem + SM_STAGE + 32768 + (r0 * 64 + cp) * 4) = l;
            split2(fmaxf(F.c[mt][nt][2] + b0, 0.f), fmaxf(F.c[mt][nt][3] + b1v, 0.f), h, l);
            *(uint32_t*)(smem + SM_STAGE + (r1 * 64 + cp) * 4) = h;
            *(uint32_t*)(smem + SM_STAGE + 32768 + (r1 * 64 + cp) * 4) = l;
        }
    }
    __syncthreads();
    {
        const int rr = tid >> 1, part = tid & 1;
        if (rr < cnt - m0) {
            const size_t gro = (size_t)(base + m0 + rr) * TH + n0;
            uint16_t* HP = (uint16_t*)g_h_hi;
            uint16_t* LP = (uint16_t*)g_h_lo;
#pragma unroll
            for (int j = 0; j < 8; j++) {
                uint4 qh = *(uint4*)(smem + SM_STAGE + (rr * 64 + part * 32 + j * 4) * 4);
                uint4 ql = *(uint4*)(smem + SM_STAGE + 32768 + (rr * 64 + part * 32 + j * 4) * 4);
                *(uint4*)(HP + gro + part * 64 + j * 8) = qh;
                *(uint4*)(LP + gro + part * 64 + j * 8) = ql;
            }
        }
    }
}

// ================= GEMM2 =================
__global__ void __launch_bounds__(NTHREADS) k_gemm2(const float* __restrict__ W2,
                                                    const float* __restrict__ b2,
                                                    float* __restrict__ out) {
    extern __shared__ char smem[];
    const int e   = blockIdx.z;
    const int cnt = g_counts[e];
    const int m0  = blockIdx.y * BM;
    if (m0 >= cnt) return;
    const int n0   = blockIdx.x * BN;
    const int base = g_offsets[e];
    const float* W = W2 + (size_t)e * TH * TO;

    const uint32_t sb = smem_to_u32(smem);
    char* tiles = smem + SM_TILES;
    const int tid = threadIdx.x, wid = tid >> 5, lane = tid & 31;
    const int wm = wid & 1, wn = wid >> 1;

    if (tid < 128) {
        *(float*)(smem + SM_BIAS + tid * 4) = b2[(size_t)e * TO + n0 + tid];
        const int rc = (m0 + tid < cnt) ? (m0 + tid) : (cnt - 1);
        *(float*)(smem + SM_PROB + tid * 4) = g_prob[g_perm[base + rc]];
    }

    const int arow = tid >> 1;
    const int half = tid & 1;
    const int arowc = (m0 + arow < cnt) ? (m0 + arow) : (cnt - 1);
    const uint16_t* hpi = (const uint16_t*)g_h_hi + (size_t)(base + arowc) * TH + half * 16;
    const uint16_t* lpi = (const uint16_t*)g_h_lo + (size_t)(base + arowc) * TH + half * 16;
    const uint32_t aso = ((uint32_t)(arow * SLD + half * 16)) * 2;

    const int n_b0 = ((wid) & 3) * 32 + lane,  kg_b0 = (wid) >> 2;
    const int n_b1 = ((wid + 8) & 3) * 32 + lane, kg_b1 = (wid + 8) >> 2;
    const float* bp0 = W + (size_t)(kg_b0 * 8) * TO + n0 + n_b0;
    const float* bp1 = W + (size_t)(kg_b1 * 8) * TO + n0 + n_b1;
    const uint32_t bo0 = ((uint32_t)(n_b0 * SLD + kg_b0 * 8)) * 2;
    const uint32_t bo1 = ((uint32_t)(n_b1 * SLD + kg_b1 * 8)) * 2;

    Frag F;
#pragma unroll
    for (int mt = 0; mt < 4; mt++)
#pragma unroll
        for (int nt = 0; nt < 4; nt++)
#pragma unroll
            for (int i = 0; i < 4; i++) F.c[mt][nt][i] = 0.f;

    uint4 qh0, qh1, ql0, ql1;
    float bw[16];

    qh0 = *(const uint4*)(hpi);
    qh1 = *(const uint4*)(hpi + 8);
    ql0 = *(const uint4*)(lpi);
    ql1 = *(const uint4*)(lpi + 8);
    load_B(bw, bp0, bp1, TO, 0);
    {
        *(uint4*)(tiles + aso) = qh0;
        *(uint4*)(tiles + aso + 16) = qh1;
        *(uint4*)(tiles + PLANE_B + aso) = ql0;
        *(uint4*)(tiles + PLANE_B + aso + 16) = ql1;
        store_B(tiles, bw, bo0, bo1);
    }
    __syncthreads();

    const int NS = TH / BK;  // 240
    for (int s = 0; s < NS; s++) {
        if (s + 1 < NS) {
            const int k0 = (s + 1) * BK;
            qh0 = *(const uint4*)(hpi + k0);
            qh1 = *(const uint4*)(hpi + k0 + 8);
            ql0 = *(const uint4*)(lpi + k0);
            ql1 = *(const uint4*)(lpi + k0 + 8);
            load_B(bw, bp0, bp1, TO, k0);
        }
        compute_stage(sb + SM_TILES + (uint32_t)(s & 1) * STAGE_B, wm, wn, lane, F);
        if (s + 1 < NS) {
            char* nb = tiles + ((s + 1) & 1) * STAGE_B;
            *(uint4*)(nb + aso) = qh0;
            *(uint4*)(nb + aso + 16) = qh1;
            *(uint4*)(nb + PLANE_B + aso) = ql0;
            *(uint4*)(nb + PLANE_B + aso + 16) = ql1;
            store_B(nb, bw, bo0, bo1);
        }
        __syncthreads();
    }

    // epilogue: (c + bias) * prob -> fp32 stage -> scattered coalesced stores
#pragma unroll
    for (int mt = 0; mt < 4; mt++) {
        const int r0 = wm * 64 + mt * 16 + (lane >> 2);
        const int r1 = r0 + 8;
        const float p0 = *(float*)(smem + SM_PROB + r0 * 4);
        const float p1 = *(float*)(smem + SM_PROB + r1 * 4);
#pragma unroll
        for (int nt = 0; nt < 4; nt++) {
            const int col = wn * 32 + nt * 8 + (lane & 3) * 2;
            float b0  = *(float*)(smem + SM_BIAS + col * 4);
            float b1v = *(float*)(smem + SM_BIAS + (col + 1) * 4);
            *(float*)(smem + SM_STAGE + (r0 * 128 + col) * 4)     = p0 * (F.c[mt][nt][0] + b0);
            *(float*)(smem + SM_STAGE + (r0 * 128 + col + 1) * 4) = p0 * (F.c[mt][nt][1] + b1v);
            *(float*)(smem + SM_STAGE + (r1 * 128 + col) * 4)     = p1 * (F.c[mt][nt][2] + b0);
            *(float*)(smem + SM_STAGE + (r1 * 128 + col + 1) * 4) = p1 * (F.c[mt][nt][3] + b1v);
        }
    }
    __syncthreads();
    {
        const int rr = tid >> 1, part = tid & 1;
        if (rr < cnt - m0) {
            const int token = g_perm[base + m0 + rr];
            float* op = out + (size_t)token * TO + n0 + part * 64;
#pragma unroll
            for (int j = 0; j < 16; j++) {
                float4 q = *(float4*)(smem + SM_STAGE + (rr * 128 + part * 64 + j * 4) * 4);
                *(float4*)(op + j * 4) = q;
            }
        }
    }
}

// ---------------------------------------------------------------
extern "C" void kernel_launch(void* const* d_in, const int* in_sizes, int n_in,
                              void* d_out, int out_size) {
    (void)in_sizes; (void)n_in; (void)out_size;
    const float* x  = (const float*)d_in[0];
    const float* Wg = (const float*)d_in[1];
    const float* bg = (const float*)d_in[2];
    const float* W1 = (const float*)d_in[3];
    const float* b1 = (const float*)d_in[4];
    const float* W2 = (const float*)d_in[5];
    const float* b2 = (const float*)d_in[6];
    float* out = (float*)d_out;

    cudaFuncSetAttribute(k_gemm1, cudaFuncAttributeMaxDynamicSharedMemorySize, SM_TOTAL);
    cudaFuncSetAttribute(k_gemm2, cudaFuncAttributeMaxDynamicSharedMemorySize, SM_TOTAL);

    k_zero<<<1, 32>>>();
    k_gate<<<(TN * 32 + 255) / 256, 256>>>(x, Wg, bg);
    k_scan<<<1, 1>>>();
    k_scatter<<<(TN + 255) / 256, 256>>>();
    k_gemm1<<<dim3(TH / BN, TN / BM, TE), NTHREADS, SM_TOTAL>>>(x, W1, b1);
    k_gemm2<<<dim3(TO / BN, TN / BM, TE), NTHREADS, SM_TOTAL>>>(W2, b2, out);
}

// round 10
// speedup vs baseline: 1.2683x; 1.0047x over previous
#include <cuda_runtime.h>
#include <cuda_bf16.h>
#include <cstdint>

#define TD 768
#define TO 768
#define TE 8
#define TH 7680
#define TN 4096

#define BM 128
#define BN 128
#define BK 32
#define NTHREADS 256
#define SLD 40                      // smem row stride in bf16 (80 B, 16B-aligned)
#define PLANE_B (128 * SLD * 2)     // 10240
#define STAGE_B (4 * PLANE_B)       // 40960

// SMEM layout (bytes)
#define SM_BIAS   0
#define SM_PROB   512
#define SM_TILES  1024
#define SM_STAGE  1024              // epilogue staging reuses tile space
#define SM_TOTAL1 (1024 + STAGE_B)      // 41984  (gemm1, single buffer, R5 had 66560 incl. stage area)
#define SM_T1     (1024 + 65536)        // keep R5's exact 66560 for gemm1 (epilogue stage needs 64KB)
#define SM_TOTAL2 (1024 + 2 * STAGE_B)  // 82944  (gemm2, double buffer)

// ---- scratch ----
__device__ int   g_counts[TE];
__device__ int   g_offsets[TE];
__device__ int   g_rank[TN];
__device__ int   g_eidx[TN];
__device__ float g_prob[TN];
__device__ int   g_perm[TN];
__device__ __nv_bfloat16 g_h_hi[(size_t)TN * TH];
__device__ __nv_bfloat16 g_h_lo[(size_t)TN * TH];
__device__ __nv_bfloat16 g_w2t_hi[(size_t)TE * TO * TH];   // [e][n][k]
__device__ __nv_bfloat16 g_w2t_lo[(size_t)TE * TO * TH];

// ================= helpers =================
__device__ __forceinline__ uint32_t smem_to_u32(const void* p) {
    uint32_t a;
    asm("{ .reg .u64 t; cvta.to.shared.u64 t, %1; cvt.u32.u64 %0, t; }" : "=r"(a) : "l"(p));
    return a;
}
__device__ __forceinline__ void ldsm4(uint32_t* r, uint32_t addr) {
    asm volatile("ldmatrix.sync.aligned.m8n8.x4.shared.b16 {%0,%1,%2,%3}, [%4];"
                 : "=r"(r[0]), "=r"(r[1]), "=r"(r[2]), "=r"(r[3]) : "r"(addr));
}
__device__ __forceinline__ void mma16816(float* c, const uint32_t* a, const uint32_t* b) {
    asm volatile("mma.sync.aligned.m16n8k16.row.col.f32.bf16.bf16.f32 "
                 "{%0,%1,%2,%3}, {%4,%5,%6,%7}, {%8,%9}, {%0,%1,%2,%3};"
                 : "+f"(c[0]), "+f"(c[1]), "+f"(c[2]), "+f"(c[3])
                 : "r"(a[0]), "r"(a[1]), "r"(a[2]), "r"(a[3]), "r"(b[0]), "r"(b[1]));
}
__device__ __forceinline__ void split2(float a, float b, uint32_t& hi, uint32_t& lo) {
    __nv_bfloat16 ah = __float2bfloat16(a);
    __nv_bfloat16 bh = __float2bfloat16(b);
    __nv_bfloat16 al = __float2bfloat16(a - __bfloat162float(ah));
    __nv_bfloat16 bl = __float2bfloat16(b - __bfloat162float(bh));
    hi = (uint32_t)__bfloat16_as_ushort(ah) | ((uint32_t)__bfloat16_as_ushort(bh) << 16);
    lo = (uint32_t)__bfloat16_as_ushort(al) | ((uint32_t)__bfloat16_as_ushort(bl) << 16);
}

#define CPA16(d, s)  asm volatile("cp.async.ca.shared.global [%0], [%1], 16;" :: "r"(d), "l"(s))
#define CP_COMMIT()  asm volatile("cp.async.commit_group;" ::: "memory")
#define CP_WAIT1()   asm volatile("cp.async.wait_group 1;" ::: "memory")
#define CP_WAIT0()   asm volatile("cp.async.wait_group 0;" ::: "memory")

// ================= gating / routing =================
__global__ void k_zero() {
    if (threadIdx.x < TE) g_counts[threadIdx.x] = 0;
}

__global__ void k_gate(const float* __restrict__ x, const float* __restrict__ Wg,
                       const float* __restrict__ bg) {
    int warp = (blockIdx.x * blockDim.x + threadIdx.x) >> 5;
    int lane = threadIdx.x & 31;
    if (warp >= TN) return;
    const float* xr = x + (size_t)warp * TD;
    float acc[TE];
#pragma unroll
    for (int e = 0; e < TE; e++) acc[e] = 0.f;
    for (int d = lane; d < TD; d += 32) {
        float xv = xr[d];
        const float* wr = Wg + (size_t)d * TE;
#pragma unroll
        for (int e = 0; e < TE; e++) acc[e] += xv * wr[e];
    }
#pragma unroll
    for (int e = 0; e < TE; e++) {
        float v = acc[e];
#pragma unroll
        for (int off = 16; off > 0; off >>= 1) v += __shfl_xor_sync(0xffffffffu, v, off);
        acc[e] = v;
    }
    if (lane == 0) {
        float mx = -1e30f; int am = 0;
#pragma unroll
        for (int e = 0; e < TE; e++) {
            float l = acc[e] + bg[e];
            acc[e] = l;
            if (l > mx) { mx = l; am = e; }
        }
        float s = 0.f;
#pragma unroll
        for (int e = 0; e < TE; e++) s += expf(acc[e] - mx);
        g_eidx[warp] = am;
        g_prob[warp] = 1.f / s;
        g_rank[warp] = atomicAdd(&g_counts[am], 1);
    }
}

// merged scan + scatter (single block)
__global__ void k_scanscatter() {
    if (threadIdx.x == 0) {
        int o = 0;
#pragma unroll
        for (int e = 0; e < TE; e++) { g_offsets[e] = o; o += g_counts[e]; }
    }
    __syncthreads();
    for (int n = threadIdx.x; n < TN; n += blockDim.x)
        g_perm[g_offsets[g_eidx[n]] + g_rank[n]] = n;
}

// ================= W2 pre-convert: [e][k][n] fp32 -> [e][n][k] bf16 hi/lo =================
__global__ void k_convert_w2(const float* __restrict__ W2) {
    __shared__ uint16_t shh[32][36];
    __shared__ uint16_t shl[32][36];
    const int n0 = blockIdx.x * 32, k0 = blockIdx.y * 32, e = blockIdx.z;
    const float* Wp = W2 + (size_t)e * TH * TO;
    const int t = threadIdx.x, tx = t & 31, ty = t >> 5;
#pragma unroll
    for (int q = 0; q < 4; q++) {
        const int k = ty * 4 + q;
        float v = Wp[(size_t)(k0 + k) * TO + n0 + tx];
        __nv_bfloat16 hb = __float2bfloat16(v);
        shh[tx][k] = __bfloat16_as_ushort(hb);
        shl[tx][k] = __bfloat16_as_ushort(__float2bfloat16(v - __bfloat162float(hb)));
    }
    __syncthreads();
    const int n = t >> 3, c = t & 7;
    const size_t off = (size_t)e * TO * TH + (size_t)(n0 + n) * TH + k0 + c * 4;
    *(uint2*)((uint16_t*)g_w2t_hi + off) = *(uint2*)&shh[n][c * 4];
    *(uint2*)((uint16_t*)g_w2t_lo + off) = *(uint2*)&shl[n][c * 4];
}

// ================= mma compute core (identical to passing R5) =================
struct Frag { float c[4][4][4]; };

__device__ __forceinline__ void compute_stage(uint32_t tb, int wm, int wn, int lane,
                                              Frag& F) {
    const uint32_t aoff = ((uint32_t)((wm * 64 + (lane & 15)) * SLD + (lane >> 4) * 8)) * 2;
    const uint32_t boff = ((uint32_t)((wn * 32 + ((lane >> 4) & 1) * 8 + (lane & 7)) * SLD
                                      + ((lane >> 3) & 1) * 8)) * 2;
    const uint32_t aHi = tb + aoff;
    const uint32_t aLo = tb + PLANE_B + aoff;
    const uint32_t bHi = tb + 2 * PLANE_B + boff;
    const uint32_t bLo = tb + 3 * PLANE_B + boff;
#pragma unroll
    for (int ks = 0; ks < 2; ks++) {
        const uint32_t kso = ks * 32;
        uint32_t ah[4][4], bh[2][4];
#pragma unroll
        for (int mt = 0; mt < 4; mt++) ldsm4(ah[mt], aHi + mt * 16 * SLD * 2 + kso);
#pragma unroll
        for (int p = 0; p < 2; p++) ldsm4(bh[p], bHi + p * 16 * SLD * 2 + kso);
#pragma unroll
        for (int mt = 0; mt < 4; mt++)
#pragma unroll
            for (int nt = 0; nt < 4; nt++)
                mma16816(F.c[mt][nt], ah[mt], &bh[nt >> 1][(nt & 1) * 2]);
        uint32_t bl[2][4];
#pragma unroll
        for (int p = 0; p < 2; p++) ldsm4(bl[p], bLo + p * 16 * SLD * 2 + kso);
#pragma unroll
        for (int mt = 0; mt < 4; mt++)
#pragma unroll
            for (int nt = 0; nt < 4; nt++)
                mma16816(F.c[mt][nt], ah[mt], &bl[nt >> 1][(nt & 1) * 2]);
        uint32_t al[4][4];
#pragma unroll
        for (int mt = 0; mt < 4; mt++) ldsm4(al[mt], aLo + mt * 16 * SLD * 2 + kso);
#pragma unroll
        for (int mt = 0; mt < 4; mt++)
#pragma unroll
            for (int nt = 0; nt < 4; nt++)
                mma16816(F.c[mt][nt], al[mt], &bh[nt >> 1][(nt & 1) * 2]);
    }
}

// ---- R5 B-tile fill for GEMM1: Bs[n][k] hi/lo from W[k][n] (coalesced, lane = n) ----
__device__ __forceinline__ void fill_B(char* smem, const float* __restrict__ W,
                                       int ldW, int n0, int k0, int wid, int lane) {
#pragma unroll
    for (int it = 0; it < 2; it++) {
        const int tsk = wid + it * 8;
        const int ng = tsk & 3, kg = tsk >> 2;
        const int n = ng * 32 + lane;
        const float* wp = W + (size_t)(k0 + kg * 8) * ldW + n0 + n;
        uint32_t hi[4], lo[4];
#pragma unroll
        for (int kk = 0; kk < 4; kk++) {
            float w0 = wp[(size_t)(2 * kk) * ldW];
            float w1 = wp[(size_t)(2 * kk + 1) * ldW];
            split2(w0, w1, hi[kk], lo[kk]);
        }
        const uint32_t o = ((uint32_t)(n * SLD + kg * 8)) * 2;
        *(uint4*)(smem + SM_TILES + 2 * PLANE_B + o) = *(uint4*)hi;
        *(uint4*)(smem + SM_TILES + 3 * PLANE_B + o) = *(uint4*)lo;
    }
}

// ================= GEMM1 (R5 structure, verbatim behavior) =================
__global__ void __launch_bounds__(NTHREADS) k_gemm1(const float* __restrict__ x,
                                                    const float* __restrict__ W1,
                                                    const float* __restrict__ b1) {
    extern __shared__ char smem[];
    const int e   = blockIdx.z;
    const int cnt = g_counts[e];
    const int m0  = blockIdx.y * BM;
    if (m0 >= cnt) return;
    const int n0   = blockIdx.x * BN;
    const int base = g_offsets[e];
    const float* W = W1 + (size_t)e * TD * TH;

    const uint32_t sb = smem_to_u32(smem);
    const int tid = threadIdx.x, wid = tid >> 5, lane = tid & 31;
    const int wm = wid & 1, wn = wid >> 1;

    if (tid < 128) *(float*)(smem + SM_BIAS + tid * 4) = b1[(size_t)e * TH + n0 + tid];

    const int arow = tid >> 1;
    const int half = tid & 1;
    const int arowc = (m0 + arow < cnt) ? (m0 + arow) : (cnt - 1);
    const float* aptr = x + (size_t)g_perm[base + arowc] * TD + half * 16;

    Frag F;
#pragma unroll
    for (int mt = 0; mt < 4; mt++)
#pragma unroll
        for (int nt = 0; nt < 4; nt++)
#pragma unroll
            for (int i = 0; i < 4; i++) F.c[mt][nt][i] = 0.f;

    __syncthreads();
    for (int s = 0; s < TD / BK; s++) {
        const int k0 = s * BK;
#pragma unroll
        for (int q = 0; q < 4; q++) {
            float4 v = *(const float4*)(aptr + k0 + q * 4);
            uint32_t h0, l0, h1, l1;
            split2(v.x, v.y, h0, l0);
            split2(v.z, v.w, h1, l1);
            const uint32_t o = ((uint32_t)(arow * SLD + half * 16 + q * 4)) * 2;
            *(uint32_t*)(smem + SM_TILES + o) = h0;
            *(uint32_t*)(smem + SM_TILES + o + 4) = h1;
            *(uint32_t*)(smem + SM_TILES + PLANE_B + o) = l0;
            *(uint32_t*)(smem + SM_TILES + PLANE_B + o + 4) = l1;
        }
        fill_B(smem, W, TH, n0, k0, wid, lane);
        __syncthreads();
        compute_stage(sb + SM_TILES, wm, wn, lane, F);
        __syncthreads();
    }

    // epilogue: relu(+bias) -> bf16 hi/lo staged -> coalesced g_h stores
#pragma unroll
    for (int mt = 0; mt < 4; mt++) {
        const int r0 = wm * 64 + mt * 16 + (lane >> 2);
        const int r1 = r0 + 8;
#pragma unroll
        for (int nt = 0; nt < 4; nt++) {
            const int cp = wn * 16 + nt * 4 + (lane & 3);
            float b0  = *(float*)(smem + SM_BIAS + (2 * cp) * 4);
            float b1v = *(float*)(smem + SM_BIAS + (2 * cp + 1) * 4);
            uint32_t h, l;
            split2(fmaxf(F.c[mt][nt][0] + b0, 0.f), fmaxf(F.c[mt][nt][1] + b1v, 0.f), h, l);
            *(uint32_t*)(smem + SM_STAGE + (r0 * 64 + cp) * 4) = h;
            *(uint32_t*)(smem + SM_STAGE + 32768 + (r0 * 64 + cp) * 4) = l;
            split2(fmaxf(F.c[mt][nt][2] + b0, 0.f), fmaxf(F.c[mt][nt][3] + b1v, 0.f), h, l);
            *(uint32_t*)(smem + SM_STAGE + (r1 * 64 + cp) * 4) = h;
            *(uint32_t*)(smem + SM_STAGE + 32768 + (r1 * 64 + cp) * 4) = l;
        }
    }
    __syncthreads();
    {
        const int rr = tid >> 1, part = tid & 1;
        if (rr < cnt - m0) {
            const size_t gro = (size_t)(base + m0 + rr) * TH + n0;
            uint16_t* HP = (uint16_t*)g_h_hi;
            uint16_t* LP = (uint16_t*)g_h_lo;
#pragma unroll
            for (int j = 0; j < 8; j++) {
                uint4 qh = *(uint4*)(smem + SM_STAGE + (rr * 64 + part * 32 + j * 4) * 4);
                uint4 ql = *(uint4*)(smem + SM_STAGE + 32768 + (rr * 64 + part * 32 + j * 4) * 4);
                *(uint4*)(HP + gro + part * 64 + j * 8) = qh;
                *(uint4*)(LP + gro + part * 64 + j * 8) = ql;
            }
        }
    }
}

// ================= GEMM2: copy-only cp.async double-buffered pipeline =================
__global__ void __launch_bounds__(NTHREADS) k_gemm2(const float* __restrict__ b2,
                                                    float* __restrict__ out) {
    extern __shared__ char smem[];
    const int e   = blockIdx.z;
    const int cnt = g_counts[e];
    const int m0  = blockIdx.y * BM;
    if (m0 >= cnt) return;
    const int n0   = blockIdx.x * BN;
    const int base = g_offsets[e];

    const uint32_t sb = smem_to_u32(smem);
    const int tid = threadIdx.x, wid = tid >> 5, lane = tid & 31;
    const int wm = wid & 1, wn = wid >> 1;

    if (tid < 128) {
        *(float*)(smem + SM_BIAS + tid * 4) = b2[(size_t)e * TO + n0 + tid];
        const int rc = (m0 + tid < cnt) ? (m0 + tid) : (cnt - 1);
        *(float*)(smem + SM_PROB + tid * 4) = g_prob[g_perm[base + rc]];
    }

    const int r = tid >> 1, h = tid & 1;
    const int rowc = (m0 + r < cnt) ? (m0 + r) : (cnt - 1);
    const char* aH = (const char*)(g_h_hi + (size_t)(base + rowc) * TH) + h * 32;
    const char* aL = (const char*)(g_h_lo + (size_t)(base + rowc) * TH) + h * 32;
    const char* bH = (const char*)(g_w2t_hi + (size_t)e * TO * TH + (size_t)(n0 + r) * TH) + h * 32;
    const char* bL = (const char*)(g_w2t_lo + (size_t)e * TO * TH + (size_t)(n0 + r) * TH) + h * 32;
    const uint32_t dst = sb + SM_TILES + (uint32_t)(r * 80 + h * 32);

    Frag F;
#pragma unroll
    for (int mt = 0; mt < 4; mt++)
#pragma unroll
        for (int nt = 0; nt < 4; nt++)
#pragma unroll
            for (int i = 0; i < 4; i++) F.c[mt][nt][i] = 0.f;

    const int NS = TH / BK;  // 240
    // prefetch stage 0
    {
        const uint32_t d = dst;
        CPA16(d, aH);                      CPA16(d + 16, aH + 16);
        CPA16(d + PLANE_B, aL);            CPA16(d + PLANE_B + 16, aL + 16);
        CPA16(d + 2 * PLANE_B, bH);        CPA16(d + 2 * PLANE_B + 16, bH + 16);
        CPA16(d + 3 * PLANE_B, bL);        CPA16(d + 3 * PLANE_B + 16, bL + 16);
        CP_COMMIT();
    }
    for (int s = 0; s < NS; s++) {
        if (s + 1 < NS) {
            const uint32_t d  = dst + (uint32_t)((s + 1) & 1) * STAGE_B;
            const uint32_t ko = (uint32_t)(s + 1) * 64;
            CPA16(d, aH + ko);                 CPA16(d + 16, aH + ko + 16);
            CPA16(d + PLANE_B, aL + ko);       CPA16(d + PLANE_B + 16, aL + ko + 16);
            CPA16(d + 2 * PLANE_B, bH + ko);   CPA16(d + 2 * PLANE_B + 16, bH + ko + 16);
            CPA16(d + 3 * PLANE_B, bL + ko);   CPA16(d + 3 * PLANE_B + 16, bL + ko + 16);
            CP_COMMIT();
            CP_WAIT1();
        } else {
            CP_WAIT0();
        }
        __syncthreads();
        compute_stage(sb + SM_TILES + (uint32_t)(s & 1) * STAGE_B, wm, wn, lane, F);
        __syncthreads();
    }

    // epilogue: (c + bias) * prob -> fp32 stage -> scattered coalesced stores
#pragma unroll
    for (int mt = 0; mt < 4; mt++) {
        const int r0 = wm * 64 + mt * 16 + (lane >> 2);
        const int r1 = r0 + 8;
        const float p0 = *(float*)(smem + SM_PROB + r0 * 4);
        const float p1 = *(float*)(smem + SM_PROB + r1 * 4);
#pragma unroll
        for (int nt = 0; nt < 4; nt++) {
            const int col = wn * 32 + nt * 8 + (lane & 3) * 2;
            float b0  = *(float*)(smem + SM_BIAS + col * 4);
            float b1v = *(float*)(smem + SM_BIAS + (col + 1) * 4);
            *(float*)(smem + SM_STAGE + (r0 * 128 + col) * 4)     = p0 * (F.c[mt][nt][0] + b0);
            *(float*)(smem + SM_STAGE + (r0 * 128 + col + 1) * 4) = p0 * (F.c[mt][nt][1] + b1v);
            *(float*)(smem + SM_STAGE + (r1 * 128 + col) * 4)     = p1 * (F.c[mt][nt][2] + b0);
            *(float*)(smem + SM_STAGE + (r1 * 128 + col + 1) * 4) = p1 * (F.c[mt][nt][3] + b1v);
        }
    }
    __syncthreads();
    {
        const int rr = tid >> 1, part = tid & 1;
        if (rr < cnt - m0) {
            const int token = g_perm[base + m0 + rr];
            float* op = out + (size_t)token * TO + n0 + part * 64;
#pragma unroll
            for (int j = 0; j < 16; j++) {
                float4 q = *(float4*)(smem + SM_STAGE + (rr * 128 + part * 64 + j * 4) * 4);
                *(float4*)(op + j * 4) = q;
            }
        }
    }
}

// ---------------------------------------------------------------
extern "C" void kernel_launch(void* const* d_in, const int* in_sizes, int n_in,
                              void* d_out, int out_size) {
    (void)in_sizes; (void)n_in; (void)out_size;
    const float* x  = (const float*)d_in[0];
    const float* Wg = (const float*)d_in[1];
    const float* bg = (const float*)d_in[2];
    const float* W1 = (const float*)d_in[3];
    const float* b1 = (const float*)d_in[4];
    const float* W2 = (const float*)d_in[5];
    const float* b2 = (const float*)d_in[6];
    float* out = (float*)d_out;

    cudaFuncSetAttribute(k_gemm1, cudaFuncAttributeMaxDynamicSharedMemorySize, SM_T1);
    cudaFuncSetAttribute(k_gemm2, cudaFuncAttributeMaxDynamicSharedMemorySize, SM_TOTAL2);

    k_zero<<<1, 32>>>();
    k_gate<<<(TN * 32 + 255) / 256, 256>>>(x, Wg, bg);
    k_scanscatter<<<1, 256>>>();
    k_gemm1<<<dim3(TH / BN, TN / BM, TE), NTHREADS, SM_T1>>>(x, W1, b1);
    k_convert_w2<<<dim3(TO / 32, TH / 32, TE), 256>>>(W2);
    k_gemm2<<<dim3(TO / BN, TN / BM, TE), NTHREADS, SM_TOTAL2>>>(b2, out);
}

// round 11
// speedup vs baseline: 1.7423x; 1.3738x over previous
#include <cuda_runtime.h>
#include <cuda_fp16.h>
#include <cstdint>

#define TD 768
#define TO 768
#define TE 8
#define TH 7680
#define TN 4096

#define BM 128
#define BN 128
#define BK 32
#define NTHREADS 256
#define SLD 40                      // smem row stride in fp16 (80 B, 16B-aligned)
#define PLANE_B (128 * SLD * 2)     // 10240
#define STAGE3_B (3 * PLANE_B)      // 30720 (A, Bhi, Blo)

// SMEM layout (bytes)
#define SM_BIAS   0
#define SM_PROB   512
#define SM_TILES  1024
#define SM_STAGE  1024                    // epilogue staging reuses tile space
#define SM_T1     (1024 + 32768)          // 33792 (gemm1: tiles 30720 / h-stage 32768)
#define SM_TOTAL2 (1024 + 65536)          // 66560 (gemm2: 2x30720 tiles / fp32 stage 65536)

// ---- scratch ----
__device__ int   g_counts[TE];
__device__ int   g_offsets[TE];
__device__ int   g_rank[TN];
__device__ int   g_eidx[TN];
__device__ float g_prob[TN];
__device__ int   g_perm[TN];
__device__ __half g_h[(size_t)TN * TH];                  // single fp16 plane
__device__ __half g_w2t_hi[(size_t)TE * TO * TH];        // [e][n][k]
__device__ __half g_w2t_lo[(size_t)TE * TO * TH];

// ================= helpers =================
__device__ __forceinline__ uint32_t smem_to_u32(const void* p) {
    uint32_t a;
    asm("{ .reg .u64 t; cvta.to.shared.u64 t, %1; cvt.u32.u64 %0, t; }" : "=r"(a) : "l"(p));
    return a;
}
__device__ __forceinline__ void ldsm4(uint32_t* r, uint32_t addr) {
    asm volatile("ldmatrix.sync.aligned.m8n8.x4.shared.b16 {%0,%1,%2,%3}, [%4];"
                 : "=r"(r[0]), "=r"(r[1]), "=r"(r[2]), "=r"(r[3]) : "r"(addr));
}
__device__ __forceinline__ void mma16816(float* c, const uint32_t* a, const uint32_t* b) {
    asm volatile("mma.sync.aligned.m16n8k16.row.col.f32.f16.f16.f32 "
                 "{%0,%1,%2,%3}, {%4,%5,%6,%7}, {%8,%9}, {%0,%1,%2,%3};"
                 : "+f"(c[0]), "+f"(c[1]), "+f"(c[2]), "+f"(c[3])
                 : "r"(a[0]), "r"(a[1]), "r"(a[2]), "r"(a[3]), "r"(b[0]), "r"(b[1]));
}
__device__ __forceinline__ uint32_t packh2(float a, float b) {
    __half2 h = __floats2half2_rn(a, b);
    return *(uint32_t*)&h;
}
// fp16 hi/lo split of a pair -> packed half2 words
__device__ __forceinline__ void splith2(float a, float b, uint32_t& hi, uint32_t& lo) {
    __half ah = __float2half_rn(a), bh = __float2half_rn(b);
    __half al = __float2half_rn(a - __half2float(ah));
    __half bl = __float2half_rn(b - __half2float(bh));
    hi = (uint32_t)*(uint16_t*)&ah | ((uint32_t)*(uint16_t*)&bh << 16);
    lo = (uint32_t)*(uint16_t*)&al | ((uint32_t)*(uint16_t*)&bl << 16);
}

#define CPA16(d, s)  asm volatile("cp.async.ca.shared.global [%0], [%1], 16;" :: "r"(d), "l"(s))
#define CP_COMMIT()  asm volatile("cp.async.commit_group;" ::: "memory")
#define CP_WAIT1()   asm volatile("cp.async.wait_group 1;" ::: "memory")
#define CP_WAIT0()   asm volatile("cp.async.wait_group 0;" ::: "memory")

// ================= gating / routing =================
__global__ void k_zero() {
    if (threadIdx.x < TE) g_counts[threadIdx.x] = 0;
}

__global__ void k_gate(const float* __restrict__ x, const float* __restrict__ Wg,
                       const float* __restrict__ bg) {
    int warp = (blockIdx.x * blockDim.x + threadIdx.x) >> 5;
    int lane = threadIdx.x & 31;
    if (warp >= TN) return;
    const float* xr = x + (size_t)warp * TD;
    float acc[TE];
#pragma unroll
    for (int e = 0; e < TE; e++) acc[e] = 0.f;
    for (int d = lane; d < TD; d += 32) {
        float xv = xr[d];
        const float* wr = Wg + (size_t)d * TE;
#pragma unroll
        for (int e = 0; e < TE; e++) acc[e] += xv * wr[e];
    }
#pragma unroll
    for (int e = 0; e < TE; e++) {
        float v = acc[e];
#pragma unroll
        for (int off = 16; off > 0; off >>= 1) v += __shfl_xor_sync(0xffffffffu, v, off);
        acc[e] = v;
    }
    if (lane == 0) {
        float mx = -1e30f; int am = 0;
#pragma unroll
        for (int e = 0; e < TE; e++) {
            float l = acc[e] + bg[e];
            acc[e] = l;
            if (l > mx) { mx = l; am = e; }
        }
        float s = 0.f;
#pragma unroll
        for (int e = 0; e < TE; e++) s += expf(acc[e] - mx);
        g_eidx[warp] = am;
        g_prob[warp] = 1.f / s;
        g_rank[warp] = atomicAdd(&g_counts[am], 1);
    }
}

__global__ void k_scanscatter() {
    if (threadIdx.x == 0) {
        int o = 0;
#pragma unroll
        for (int e = 0; e < TE; e++) { g_offsets[e] = o; o += g_counts[e]; }
    }
    __syncthreads();
    for (int n = threadIdx.x; n < TN; n += blockDim.x)
        g_perm[g_offsets[g_eidx[n]] + g_rank[n]] = n;
}

// ================= W2 pre-convert: [e][k][n] fp32 -> [e][n][k] fp16 hi/lo =================
__global__ void k_convert_w2(const float* __restrict__ W2) {
    __shared__ uint16_t shh[32][36];
    __shared__ uint16_t shl[32][36];
    const int n0 = blockIdx.x * 32, k0 = blockIdx.y * 32, e = blockIdx.z;
    const float* Wp = W2 + (size_t)e * TH * TO;
    const int t = threadIdx.x, tx = t & 31, ty = t >> 5;
#pragma unroll
    for (int q = 0; q < 4; q++) {
        const int k = ty * 4 + q;
        float v = Wp[(size_t)(k0 + k) * TO + n0 + tx];
        __half hb = __float2half_rn(v);
        __half lb = __float2half_rn(v - __half2float(hb));
        shh[tx][k] = *(uint16_t*)&hb;
        shl[tx][k] = *(uint16_t*)&lb;
    }
    __syncthreads();
    const int n = t >> 3, c = t & 7;
    const size_t off = (size_t)e * TO * TH + (size_t)(n0 + n) * TH + k0 + c * 4;
    *(uint2*)((uint16_t*)g_w2t_hi + off) = *(uint2*)&shh[n][c * 4];
    *(uint2*)((uint16_t*)g_w2t_lo + off) = *(uint2*)&shl[n][c * 4];
}

// ================= 2-pass fp16 mma core: D += A*(Bhi) + A*(Blo) =================
struct Frag { float c[4][4][4]; };

__device__ __forceinline__ void compute2(uint32_t tb, int wm, int wn, int lane, Frag& F) {
    const uint32_t aoff = ((uint32_t)((wm * 64 + (lane & 15)) * SLD + (lane >> 4) * 8)) * 2;
    const uint32_t boff = ((uint32_t)((wn * 32 + ((lane >> 4) & 1) * 8 + (lane & 7)) * SLD
                                      + ((lane >> 3) & 1) * 8)) * 2;
    const uint32_t aP = tb + aoff;
    const uint32_t bH = tb + PLANE_B + boff;
    const uint32_t bL = tb + 2 * PLANE_B + boff;
#pragma unroll
    for (int ks = 0; ks < 2; ks++) {
        const uint32_t kso = ks * 32;
        uint32_t ah[4][4], bh[2][4];
#pragma unroll
        for (int mt = 0; mt < 4; mt++) ldsm4(ah[mt], aP + mt * 16 * SLD * 2 + kso);
#pragma unroll
        for (int p = 0; p < 2; p++) ldsm4(bh[p], bH + p * 16 * SLD * 2 + kso);
#pragma unroll
        for (int mt = 0; mt < 4; mt++)
#pragma unroll
            for (int nt = 0; nt < 4; nt++)
                mma16816(F.c[mt][nt], ah[mt], &bh[nt >> 1][(nt & 1) * 2]);
        uint32_t bl[2][4];
#pragma unroll
        for (int p = 0; p < 2; p++) ldsm4(bl[p], bL + p * 16 * SLD * 2 + kso);
#pragma unroll
        for (int mt = 0; mt < 4; mt++)
#pragma unroll
            for (int nt = 0; nt < 4; nt++)
                mma16816(F.c[mt][nt], ah[mt], &bl[nt >> 1][(nt & 1) * 2]);
    }
}

// ================= GEMM1: in-kernel convert (R5 structure), fp16 2-pass =================
__global__ void __launch_bounds__(NTHREADS) k_gemm1(const float* __restrict__ x,
                                                    const float* __restrict__ W1,
                                                    const float* __restrict__ b1) {
    extern __shared__ char smem[];
    const int e   = blockIdx.z;
    const int cnt = g_counts[e];
    const int m0  = blockIdx.y * BM;
    if (m0 >= cnt) return;
    const int n0   = blockIdx.x * BN;
    const int base = g_offsets[e];
    const float* W = W1 + (size_t)e * TD * TH;

    const uint32_t sb = smem_to_u32(smem);
    const int tid = threadIdx.x, wid = tid >> 5, lane = tid & 31;
    const int wm = wid & 1, wn = wid >> 1;

    if (tid < 128) *(float*)(smem + SM_BIAS + tid * 4) = b1[(size_t)e * TH + n0 + tid];

    const int arow = tid >> 1;
    const int half = tid & 1;
    const int arowc = (m0 + arow < cnt) ? (m0 + arow) : (cnt - 1);
    const float* aptr = x + (size_t)g_perm[base + arowc] * TD + half * 16;

    Frag F;
#pragma unroll
    for (int mt = 0; mt < 4; mt++)
#pragma unroll
        for (int nt = 0; nt < 4; nt++)
#pragma unroll
            for (int i = 0; i < 4; i++) F.c[mt][nt][i] = 0.f;

    __syncthreads();
    for (int s = 0; s < TD / BK; s++) {
        const int k0 = s * BK;
        // A fill: 16 fp32 -> 8 packed fp16 words (single plane)
#pragma unroll
        for (int q = 0; q < 4; q++) {
            float4 v = *(const float4*)(aptr + k0 + q * 4);
            const uint32_t o = ((uint32_t)(arow * SLD + half * 16 + q * 4)) * 2;
            *(uint32_t*)(smem + SM_TILES + o)     = packh2(v.x, v.y);
            *(uint32_t*)(smem + SM_TILES + o + 4) = packh2(v.z, v.w);
        }
        // B fill: W[k][n] fp32 -> Bs[n][k] fp16 hi/lo
#pragma unroll
        for (int it = 0; it < 2; it++) {
            const int tsk = wid + it * 8;
            const int ng = tsk & 3, kg = tsk >> 2;
            const int n = ng * 32 + lane;
            const float* wp = W + (size_t)(k0 + kg * 8) * TH + n0 + n;
            uint32_t hi[4], lo[4];
#pragma unroll
            for (int kk = 0; kk < 4; kk++) {
                float w0 = wp[(size_t)(2 * kk) * TH];
                float w1 = wp[(size_t)(2 * kk + 1) * TH];
                splith2(w0, w1, hi[kk], lo[kk]);
            }
            const uint32_t o = ((uint32_t)(n * SLD + kg * 8)) * 2;
            *(uint4*)(smem + SM_TILES + PLANE_B + o)     = *(uint4*)hi;
            *(uint4*)(smem + SM_TILES + 2 * PLANE_B + o) = *(uint4*)lo;
        }
        __syncthreads();
        compute2(sb + SM_TILES, wm, wn, lane, F);
        __syncthreads();
    }

    // epilogue: relu(+bias) -> fp16 staged -> coalesced g_h stores
#pragma unroll
    for (int mt = 0; mt < 4; mt++) {
        const int r0 = wm * 64 + mt * 16 + (lane >> 2);
        const int r1 = r0 + 8;
#pragma unroll
        for (int nt = 0; nt < 4; nt++) {
            const int cp = wn * 16 + nt * 4 + (lane & 3);
            float b0  = *(float*)(smem + SM_BIAS + (2 * cp) * 4);
            float b1v = *(float*)(smem + SM_BIAS + (2 * cp + 1) * 4);
            *(uint32_t*)(smem + SM_STAGE + (r0 * 64 + cp) * 4) =
                packh2(fmaxf(F.c[mt][nt][0] + b0, 0.f), fmaxf(F.c[mt][nt][1] + b1v, 0.f));
            *(uint32_t*)(smem + SM_STAGE + (r1 * 64 + cp) * 4) =
                packh2(fmaxf(F.c[mt][nt][2] + b0, 0.f), fmaxf(F.c[mt][nt][3] + b1v, 0.f));
        }
    }
    __syncthreads();
    {
        const int rr = tid >> 1, part = tid & 1;
        if (rr < cnt - m0) {
            uint16_t* HP = (uint16_t*)g_h + (size_t)(base + m0 + rr) * TH + n0 + part * 64;
#pragma unroll
            for (int j = 0; j < 8; j++) {
                uint4 q = *(uint4*)(smem + SM_STAGE + (rr * 64 + part * 32 + j * 4) * 4);
                *(uint4*)(HP + j * 8) = q;
            }
        }
    }
}

// ================= GEMM2: copy-only cp.async double-buffered, fp16 2-pass =================
__global__ void __launch_bounds__(NTHREADS) k_gemm2(const float* __restrict__ b2,
                                                    float* __restrict__ out) {
    extern __shared__ char smem[];
    const int e   = blockIdx.z;
    const int cnt = g_counts[e];
    const int m0  = blockIdx.y * BM;
    if (m0 >= cnt) return;
    const int n0   = blockIdx.x * BN;
    const int base = g_offsets[e];

    const uint32_t sb = smem_to_u32(smem);
    const int tid = threadIdx.x, wid = tid >> 5, lane = tid & 31;
    const int wm = wid & 1, wn = wid >> 1;

    if (tid < 128) {
        *(float*)(smem + SM_BIAS + tid * 4) = b2[(size_t)e * TO + n0 + tid];
        const int rc = (m0 + tid < cnt) ? (m0 + tid) : (cnt - 1);
        *(float*)(smem + SM_PROB + tid * 4) = g_prob[g_perm[base + rc]];
    }

    const int r = tid >> 1, h = tid & 1;
    const int rowc = (m0 + r < cnt) ? (m0 + r) : (cnt - 1);
    const char* aP = (const char*)(g_h + (size_t)(base + rowc) * TH) + h * 32;
    const char* bH = (const char*)(g_w2t_hi + (size_t)e * TO * TH + (size_t)(n0 + r) * TH) + h * 32;
    const char* bL = (const char*)(g_w2t_lo + (size_t)e * TO * TH + (size_t)(n0 + r) * TH) + h * 32;
    const uint32_t dst = sb + SM_TILES + (uint32_t)(r * 80 + h * 32);

    Frag F;
#pragma unroll
    for (int mt = 0; mt < 4; mt++)
#pragma unroll
        for (int nt = 0; nt < 4; nt++)
#pragma unroll
            for (int i = 0; i < 4; i++) F.c[mt][nt][i] = 0.f;

    const int NS = TH / BK;  // 240
    {
        CPA16(dst, aP);                          CPA16(dst + 16, aP + 16);
        CPA16(dst + PLANE_B, bH);                CPA16(dst + PLANE_B + 16, bH + 16);
        CPA16(dst + 2 * PLANE_B, bL);            CPA16(dst + 2 * PLANE_B + 16, bL + 16);
        CP_COMMIT();
    }
    for (int s = 0; s < NS; s++) {
        if (s + 1 < NS) {
            const uint32_t d  = dst + (uint32_t)((s + 1) & 1) * STAGE3_B;
            const uint32_t ko = (uint32_t)(s + 1) * 64;
            CPA16(d, aP + ko);                    CPA16(d + 16, aP + ko + 16);
            CPA16(d + PLANE_B, bH + ko);          CPA16(d + PLANE_B + 16, bH + ko + 16);
            CPA16(d + 2 * PLANE_B, bL + ko);      CPA16(d + 2 * PLANE_B + 16, bL + ko + 16);
            CP_COMMIT();
            CP_WAIT1();
        } else {
            CP_WAIT0();
        }
        __syncthreads();
        compute2(sb + SM_TILES + (uint32_t)(s & 1) * STAGE3_B, wm, wn, lane, F);
        __syncthreads();
    }

    // epilogue: (c + bias) * prob -> fp32 stage -> scattered coalesced stores
#pragma unroll
    for (int mt = 0; mt < 4; mt++) {
        const int r0 = wm * 64 + mt * 16 + (lane >> 2);
        const int r1 = r0 + 8;
        const float p0 = *(float*)(smem + SM_PROB + r0 * 4);
        const float p1 = *(float*)(smem + SM_PROB + r1 * 4);
#pragma unroll
        for (int nt = 0; nt < 4; nt++) {
            const int col = wn * 32 + nt * 8 + (lane & 3) * 2;
            float b0  = *(float*)(smem + SM_BIAS + col * 4);
            float b1v = *(float*)(smem + SM_BIAS + (col + 1) * 4);
            *(float*)(smem + SM_STAGE + (r0 * 128 + col) * 4)     = p0 * (F.c[mt][nt][0] + b0);
            *(float*)(smem + SM_STAGE + (r0 * 128 + col + 1) * 4) = p0 * (F.c[mt][nt][1] + b1v);
            *(float*)(smem + SM_STAGE + (r1 * 128 + col) * 4)     = p1 * (F.c[mt][nt][2] + b0);
            *(float*)(smem + SM_STAGE + (r1 * 128 + col + 1) * 4) = p1 * (F.c[mt][nt][3] + b1v);
        }
    }
    __syncthreads();
    {
        const int rr = tid >> 1, part = tid & 1;
        if (rr < cnt - m0) {
            const int token = g_perm[base + m0 + rr];
            float* op = out + (size_t)token * TO + n0 + part * 64;
#pragma unroll
            for (int j = 0; j < 16; j++) {
                float4 q = *(float4*)(smem + SM_STAGE + (rr * 128 + part * 64 + j * 4) * 4);
                *(float4*)(op + j * 4) = q;
            }
        }
    }
}

// ---------------------------------------------------------------
extern "C" void kernel_launch(void* const* d_in, const int* in_sizes, int n_in,
                              void* d_out, int out_size) {
    (void)in_sizes; (void)n_in; (void)out_size;
    const float* x  = (const float*)d_in[0];
    const float* Wg = (const float*)d_in[1];
    const float* bg = (const float*)d_in[2];
    const float* W1 = (const float*)d_in[3];
    const float* b1 = (const float*)d_in[4];
    const float* W2 = (const float*)d_in[5];
    const float* b2 = (const float*)d_in[6];
    float* out = (float*)d_out;

    cudaFuncSetAttribute(k_gemm1, cudaFuncAttributeMaxDynamicSharedMemorySize, SM_T1);
    cudaFuncSetAttribute(k_gemm2, cudaFuncAttributeMaxDynamicSharedMemorySize, SM_TOTAL2);

    k_zero<<<1, 32>>>();
    k_gate<<<(TN * 32 + 255) / 256, 256>>>(x, Wg, bg);
    k_scanscatter<<<1, 256>>>();
    k_gemm1<<<dim3(TH / BN, TN / BM, TE), NTHREADS, SM_T1>>>(x, W1, b1);
    k_convert_w2<<<dim3(TO / 32, TH / 32, TE), 256>>>(W2);
    k_gemm2<<<dim3(TO / BN, TN / BM, TE), NTHREADS, SM_TOTAL2>>>(b2, out);
}

// round 13
// speedup vs baseline: 2.2417x; 1.2866x over previous
#include <cuda_runtime.h>
#include <cuda_fp16.h>
#include <cstdint>

#define TD 768
#define TO 768
#define TE 8
#define TH 7680
#define TN 4096

#define BM 128
#define BN 128
#define BK 32
#define NTHREADS 256
#define SLD 40                      // smem row stride in fp16 (80 B, 16B-aligned)
#define PLANE_B (128 * SLD * 2)     // 10240
#define STAGE2_B (2 * PLANE_B)      // 20480 (A, Bhi)

// SMEM layout (bytes)
#define SM_BIAS   0
#define SM_PROB   512
#define SM_TILES  1024
#define SM_STAGE  1024                    // epilogue staging reuses tile space
#define SM_T1     (1024 + 32768)          // 33792 (gemm1: tiles 20480 / h-stage 32768)
#define SM_TOTAL2 (1024 + 65536)          // 66560 (gemm2: 2x20480 tiles / fp32 stage 65536)

// ---- scratch ----
__device__ int   g_counts[TE];
__device__ int   g_offsets[TE];
__device__ int   g_rank[TN];
__device__ int   g_eidx[TN];
__device__ float g_prob[TN];
__device__ int   g_perm[TN];
__device__ __half g_h[(size_t)TN * TH];                  // fp16 hidden
__device__ __half g_w2t[(size_t)TE * TO * TH];           // [e][n][k] fp16

// ================= helpers =================
__device__ __forceinline__ uint32_t smem_to_u32(const void* p) {
    uint32_t a;
    asm("{ .reg .u64 t; cvta.to.shared.u64 t, %1; cvt.u32.u64 %0, t; }" : "=r"(a) : "l"(p));
    return a;
}
__device__ __forceinline__ void ldsm4(uint32_t* r, uint32_t addr) {
    asm volatile("ldmatrix.sync.aligned.m8n8.x4.shared.b16 {%0,%1,%2,%3}, [%4];"
                 : "=r"(r[0]), "=r"(r[1]), "=r"(r[2]), "=r"(r[3]) : "r"(addr));
}
__device__ __forceinline__ void mma16816(float* c, const uint32_t* a, const uint32_t* b) {
    asm volatile("mma.sync.aligned.m16n8k16.row.col.f32.f16.f16.f32 "
                 "{%0,%1,%2,%3}, {%4,%5,%6,%7}, {%8,%9}, {%0,%1,%2,%3};"
                 : "+f"(c[0]), "+f"(c[1]), "+f"(c[2]), "+f"(c[3])
                 : "r"(a[0]), "r"(a[1]), "r"(a[2]), "r"(a[3]), "r"(b[0]), "r"(b[1]));
}
__device__ __forceinline__ uint32_t packh2(float a, float b) {
    __half2 h = __floats2half2_rn(a, b);
    return *(uint32_t*)&h;
}

#define CPA16(d, s)  asm volatile("cp.async.ca.shared.global [%0], [%1], 16;" :: "r"(d), "l"(s))
#define CP_COMMIT()  asm volatile("cp.async.commit_group;" ::: "memory")
#define CP_WAIT1()   asm volatile("cp.async.wait_group 1;" ::: "memory")
#define CP_WAIT0()   asm volatile("cp.async.wait_group 0;" ::: "memory")

// ================= gating / routing =================
__global__ void k_zero() {
    if (threadIdx.x < TE) g_counts[threadIdx.x] = 0;
}

__global__ void k_gate(const float* __restrict__ x, const float* __restrict__ Wg,
                       const float* __restrict__ bg) {
    int warp = (blockIdx.x * blockDim.x + threadIdx.x) >> 5;
    int lane = threadIdx.x & 31;
    if (warp >= TN) return;
    const float* xr = x + (size_t)warp * TD;
    float acc[TE];
#pragma unroll
    for (int e = 0; e < TE; e++) acc[e] = 0.f;
    for (int d = lane; d < TD; d += 32) {
        float xv = xr[d];
        const float* wr = Wg + (size_t)d * TE;
#pragma unroll
        for (int e = 0; e < TE; e++) acc[e] += xv * wr[e];
    }
#pragma unroll
    for (int e = 0; e < TE; e++) {
        float v = acc[e];
#pragma unroll
        for (int off = 16; off > 0; off >>= 1) v += __shfl_xor_sync(0xffffffffu, v, off);
        acc[e] = v;
    }
    if (lane == 0) {
        float mx = -1e30f; int am = 0;
#pragma unroll
        for (int e = 0; e < TE; e++) {
            float l = acc[e] + bg[e];
            acc[e] = l;
            if (l > mx) { mx = l; am = e; }
        }
        float s = 0.f;
#pragma unroll
        for (int e = 0; e < TE; e++) s += expf(acc[e] - mx);
        g_eidx[warp] = am;
        g_prob[warp] = 1.f / s;
        g_rank[warp] = atomicAdd(&g_counts[am], 1);
    }
}

__global__ void k_scanscatter() {
    if (threadIdx.x == 0) {
        int o = 0;
#pragma unroll
        for (int e = 0; e < TE; e++) { g_offsets[e] = o; o += g_counts[e]; }
    }
    __syncthreads();
    for (int n = threadIdx.x; n < TN; n += blockDim.x)
        g_perm[g_offsets[g_eidx[n]] + g_rank[n]] = n;
}

// ================= W2 pre-convert: [e][k][n] fp32 -> [e][n][k] fp16 =================
__global__ void k_convert_w2(const float* __restrict__ W2) {
    __shared__ uint16_t shh[32][36];
    const int n0 = blockIdx.x * 32, k0 = blockIdx.y * 32, e = blockIdx.z;
    const float* Wp = W2 + (size_t)e * TH * TO;
    const int t = threadIdx.x, tx = t & 31, ty = t >> 5;
#pragma unroll
    for (int q = 0; q < 4; q++) {
        const int k = ty * 4 + q;
        float v = Wp[(size_t)(k0 + k) * TO + n0 + tx];
        __half hb = __float2half_rn(v);
        shh[tx][k] = *(uint16_t*)&hb;
    }
    __syncthreads();
    const int n = t >> 3, c = t & 7;
    const size_t off = (size_t)e * TO * TH + (size_t)(n0 + n) * TH + k0 + c * 4;
    *(uint2*)((uint16_t*)g_w2t + off) = *(uint2*)&shh[n][c * 4];
}

// ================= single-pass fp16 mma core: D += A*B =================
struct Frag { float c[4][4][4]; };

__device__ __forceinline__ void compute1(uint32_t tb, int wm, int wn, int lane, Frag& F) {
    const uint32_t aoff = ((uint32_t)((wm * 64 + (lane & 15)) * SLD + (lane >> 4) * 8)) * 2;
    const uint32_t boff = ((uint32_t)((wn * 32 + ((lane >> 4) & 1) * 8 + (lane & 7)) * SLD
                                      + ((lane >> 3) & 1) * 8)) * 2;
    const uint32_t aP = tb + aoff;
    const uint32_t bP = tb + PLANE_B + boff;
#pragma unroll
    for (int ks = 0; ks < 2; ks++) {
        const uint32_t kso = ks * 32;
        uint32_t ah[4][4], bh[2][4];
#pragma unroll
        for (int mt = 0; mt < 4; mt++) ldsm4(ah[mt], aP + mt * 16 * SLD * 2 + kso);
#pragma unroll
        for (int p = 0; p < 2; p++) ldsm4(bh[p], bP + p * 16 * SLD * 2 + kso);
#pragma unroll
        for (int mt = 0; mt < 4; mt++)
#pragma unroll
            for (int nt = 0; nt < 4; nt++)
                mma16816(F.c[mt][nt], ah[mt], &bh[nt >> 1][(nt & 1) * 2]);
    }
}

// ================= GEMM1: in-kernel convert, single-pass fp16 =================
__global__ void __launch_bounds__(NTHREADS) k_gemm1(const float* __restrict__ x,
                                                    const float* __restrict__ W1,
                                                    const float* __restrict__ b1) {
    extern __shared__ char smem[];
    const int e   = blockIdx.z;
    const int cnt = g_counts[e];
    const int m0  = blockIdx.y * BM;
    if (m0 >= cnt) return;
    const int n0   = blockIdx.x * BN;
    const int base = g_offsets[e];
    const float* W = W1 + (size_t)e * TD * TH;

    const uint32_t sb = smem_to_u32(smem);
    const int tid = threadIdx.x, wid = tid >> 5, lane = tid & 31;
    const int wm = wid & 1, wn = wid >> 1;

    if (tid < 128) *(float*)(smem + SM_BIAS + tid * 4) = b1[(size_t)e * TH + n0 + tid];

    const int arow = tid >> 1;
    const int half = tid & 1;
    const int arowc = (m0 + arow < cnt) ? (m0 + arow) : (cnt - 1);
    const float* aptr = x + (size_t)g_perm[base + arowc] * TD + half * 16;

    Frag F;
#pragma unroll
    for (int mt = 0; mt < 4; mt++)
#pragma unroll
        for (int nt = 0; nt < 4; nt++)
#pragma unroll
            for (int i = 0; i < 4; i++) F.c[mt][nt][i] = 0.f;

    __syncthreads();
    for (int s = 0; s < TD / BK; s++) {
        const int k0 = s * BK;
        // A fill: 16 fp32 -> 8 packed fp16 words
#pragma unroll
        for (int q = 0; q < 4; q++) {
            float4 v = *(const float4*)(aptr + k0 + q * 4);
            const uint32_t o = ((uint32_t)(arow * SLD + half * 16 + q * 4)) * 2;
            *(uint32_t*)(smem + SM_TILES + o)     = packh2(v.x, v.y);
            *(uint32_t*)(smem + SM_TILES + o + 4) = packh2(v.z, v.w);
        }
        // B fill: W[k][n] fp32 -> Bs[n][k] fp16
#pragma unroll
        for (int it = 0; it < 2; it++) {
            const int tsk = wid + it * 8;
            const int ng = tsk & 3, kg = tsk >> 2;
            const int n = ng * 32 + lane;
            const float* wp = W + (size_t)(k0 + kg * 8) * TH + n0 + n;
            uint32_t hw[4];
#pragma unroll
            for (int kk = 0; kk < 4; kk++)
                hw[kk] = packh2(wp[(size_t)(2 * kk) * TH], wp[(size_t)(2 * kk + 1) * TH]);
            const uint32_t o = ((uint32_t)(n * SLD + kg * 8)) * 2;
            *(uint4*)(smem + SM_TILES + PLANE_B + o) = *(uint4*)hw;
        }
        __syncthreads();
        compute1(sb + SM_TILES, wm, wn, lane, F);
        __syncthreads();
    }

    // epilogue: relu(+bias) -> fp16 staged -> coalesced g_h stores
#pragma unroll
    for (int mt = 0; mt < 4; mt++) {
        const int r0 = wm * 64 + mt * 16 + (lane >> 2);
        const int r1 = r0 + 8;
#pragma unroll
        for (int nt = 0; nt < 4; nt++) {
            const int cp = wn * 16 + nt * 4 + (lane & 3);
            float b0  = *(float*)(smem + SM_BIAS + (2 * cp) * 4);
            float b1v = *(float*)(smem + SM_BIAS + (2 * cp + 1) * 4);
            *(uint32_t*)(smem + SM_STAGE + (r0 * 64 + cp) * 4) =
                packh2(fmaxf(F.c[mt][nt][0] + b0, 0.f), fmaxf(F.c[mt][nt][1] + b1v, 0.f));
            *(uint32_t*)(smem + SM_STAGE + (r1 * 64 + cp) * 4) =
                packh2(fmaxf(F.c[mt][nt][2] + b0, 0.f), fmaxf(F.c[mt][nt][3] + b1v, 0.f));
        }
    }
    __syncthreads();
    {
        const int rr = tid >> 1, part = tid & 1;
        if (rr < cnt - m0) {
            uint16_t* HP = (uint16_t*)g_h + (size_t)(base + m0 + rr) * TH + n0 + part * 64;
#pragma unroll
            for (int j = 0; j < 8; j++) {
                uint4 q = *(uint4*)(smem + SM_STAGE + (rr * 64 + part * 32 + j * 4) * 4);
                *(uint4*)(HP + j * 8) = q;
            }
        }
    }
}

// ================= GEMM2: copy-only cp.async double-buffered, single-pass fp16 =================
__global__ void __launch_bounds__(NTHREADS) k_gemm2(const float* __restrict__ b2,
                                                    float* __restrict__ out) {
    extern __shared__ char smem[];
    const int e   = blockIdx.z;
    const int cnt = g_counts[e];
    const int m0  = blockIdx.y * BM;
    if (m0 >= cnt) return;
    const int n0   = blockIdx.x * BN;
    const int base = g_offsets[e];

    const uint32_t sb = smem_to_u32(smem);
    const int tid = threadIdx.x, wid = tid >> 5, lane = tid & 31;
    const int wm = wid & 1, wn = wid >> 1;

    if (tid < 128) {
        *(float*)(smem + SM_BIAS + tid * 4) = b2[(size_t)e * TO + n0 + tid];
        const int rc = (m0 + tid < cnt) ? (m0 + tid) : (cnt - 1);
        *(float*)(smem + SM_PROB + tid * 4) = g_prob[g_perm[base + rc]];
    }

    const int r = tid >> 1, h = tid & 1;
    const int rowc = (m0 + r < cnt) ? (m0 + r) : (cnt - 1);
    const char* aP = (const char*)(g_h + (size_t)(base + rowc) * TH) + h * 32;
    const char* bP = (const char*)(g_w2t + (size_t)e * TO * TH + (size_t)(n0 + r) * TH) + h * 32;
    const uint32_t dst = sb + SM_TILES + (uint32_t)(r * 80 + h * 32);

    Frag F;
#pragma unroll
    for (int mt = 0; mt < 4; mt++)
#pragma unroll
        for (int nt = 0; nt < 4; nt++)
#pragma unroll
            for (int i = 0; i < 4; i++) F.c[mt][nt][i] = 0.f;

    const int NS = TH / BK;  // 240
    {
        CPA16(dst, aP);                CPA16(dst + 16, aP + 16);
        CPA16(dst + PLANE_B, bP);      CPA16(dst + PLANE_B + 16, bP + 16);
        CP_COMMIT();
    }
    for (int s = 0; s < NS; s++) {
        if (s + 1 < NS) {
            const uint32_t d  = dst + (uint32_t)((s + 1) & 1) * STAGE2_B;
            const uint32_t ko = (uint32_t)(s + 1) * 64;
            CPA16(d, aP + ko);             CPA16(d + 16, aP + ko + 16);
            CPA16(d + PLANE_B, bP + ko);   CPA16(d + PLANE_B + 16, bP + ko + 16);
            CP_COMMIT();
            CP_WAIT1();
        } else {
            CP_WAIT0();
        }
        __syncthreads();
        compute1(sb + SM_TILES + (uint32_t)(s & 1) * STAGE2_B, wm, wn, lane, F);
        __syncthreads();
    }

    // epilogue: (c + bias) * prob -> fp32 stage -> scattered coalesced stores
#pragma unroll
    for (int mt = 0; mt < 4; mt++) {
        const int r0 = wm * 64 + mt * 16 + (lane >> 2);
        const int r1 = r0 + 8;
        const float p0 = *(float*)(smem + SM_PROB + r0 * 4);
        const float p1 = *(float*)(smem + SM_PROB + r1 * 4);
#pragma unroll
        for (int nt = 0; nt < 4; nt++) {
            const int col = wn * 32 + nt * 8 + (lane & 3) * 2;
            float b0  = *(float*)(smem + SM_BIAS + col * 4);
            float b1v = *(float*)(smem + SM_BIAS + (col + 1) * 4);
            *(float*)(smem + SM_STAGE + (r0 * 128 + col) * 4)     = p0 * (F.c[mt][nt][0] + b0);
            *(float*)(smem + SM_STAGE + (r0 * 128 + col + 1) * 4) = p0 * (F.c[mt][nt][1] + b1v);
            *(float*)(smem + SM_STAGE + (r1 * 128 + col) * 4)     = p1 * (F.c[mt][nt][2] + b0);
            *(float*)(smem + SM_STAGE + (r1 * 128 + col + 1) * 4) = p1 * (F.c[mt][nt][3] + b1v);
        }
    }
    __syncthreads();
    {
        const int rr = tid >> 1, part = tid & 1;
        if (rr < cnt - m0) {
            const int token = g_perm[base + m0 + rr];
            float* op = out + (size_t)token * TO + n0 + part * 64;
#pragma unroll
            for (int j = 0; j < 16; j++) {
                float4 q = *(float4*)(smem + SM_STAGE + (rr * 128 + part * 64 + j * 4) * 4);
                *(float4*)(op + j * 4) = q;
            }
        }
    }
}

// ---------------------------------------------------------------
extern "C" void kernel_launch(void* const* d_in, const int* in_sizes, int n_in,
                              void* d_out, int out_size) {
    (void)in_sizes; (void)n_in; (void)out_size;
    const float* x  = (const float*)d_in[0];
    const float* Wg = (const float*)d_in[1];
    const float* bg = (const float*)d_in[2];
    const float* W1 = (const float*)d_in[3];
    const float* b1 = (const float*)d_in[4];
    const float* W2 = (const float*)d_in[5];
    const float* b2 = (const float*)d_in[6];
    float* out = (float*)d_out;

    cudaFuncSetAttribute(k_gemm1, cudaFuncAttributeMaxDynamicSharedMemorySize, SM_T1);
    cudaFuncSetAttribute(k_gemm2, cudaFuncAttributeMaxDynamicSharedMemorySize, SM_TOTAL2);

    k_zero<<<1, 32>>>();
    k_gate<<<(TN * 32 + 255) / 256, 256>>>(x, Wg, bg);
    k_scanscatter<<<1, 256>>>();
    k_gemm1<<<dim3(TH / BN, TN / BM, TE), NTHREADS, SM_T1>>>(x, W1, b1);
    k_convert_w2<<<dim3(TO / 32, TH / 32, TE), 256>>>(W2);
    k_gemm2<<<dim3(TO / BN, TN / BM, TE), NTHREADS, SM_TOTAL2>>>(b2, out);
}